// round 6
// baseline (speedup 1.0000x reference)
#include <cuda_runtime.h>
#include <cstddef>

#define BB 16
#define TT 512
#define DD 256
#define HH 4
#define HD 64
#define MM (BB*TT)          // 8192

// ---------------- scratch (static device memory; no allocs) ----------------
__device__ float g_q[MM*DD];
__device__ float g_k[MM*DD];
__device__ float g_v[MM*DD];
__device__ float g_oc[MM*DD];
__device__ float g_att[MM*DD];
__device__ float g_s[(size_t)BB*HH*TT*TT];   // 64 MB attention scores
__device__ float g_xp[TT*BB*16];             // per-step gate pre-activations
__device__ float g_hs[BB*TT*4];              // lstm hidden outputs

__device__ __forceinline__ float fsig(float x){
    float e = __expf(-x);
    return __fdividef(1.0f, 1.0f + e);
}
__device__ __forceinline__ float ftanh(float x){
    float e = __expf(2.0f*x);
    return __fdividef(e - 1.0f, e + 1.0f);
}

// ---------------- fused QKV projection: C = emb[idx] @ W^T + b ---------------
// blockIdx.z selects (W,b,C) among {Q,K,V}. M=8192, N=256, K=256.
__global__ void qkv_kernel(const float* __restrict__ emb,
                           const int*   __restrict__ idx,
                           const float* __restrict__ Wq, const float* __restrict__ bq,
                           const float* __restrict__ Wk, const float* __restrict__ bk,
                           const float* __restrict__ Wv, const float* __restrict__ bv)
{
    __shared__ float As[16][68];
    __shared__ float Bs[16][68];
    const int sel = blockIdx.z;
    const float* W    = (sel==0)?Wq:(sel==1)?Wk:Wv;
    const float* bias = (sel==0)?bq:(sel==1)?bk:bv;
    float* C          = (sel==0)?g_q:(sel==1)?g_k:g_v;
    const int tid = threadIdx.x;
    const int bm = blockIdx.x*64, bn = blockIdx.y*64;
    const int lr = tid>>2, lc = (tid&3)<<2;
    const int tr = (tid>>4)<<2, tc = (tid&15)<<2;
    const float* arow = emb + (size_t)idx[bm+lr]*DD;
    const float* brow = W + (size_t)(bn+lr)*DD;
    float acc[4][4] = {};
    for (int k0=0; k0<DD; k0+=16){
        float4 av = *(const float4*)(arow + k0 + lc);
        float4 bv4 = *(const float4*)(brow + k0 + lc);
        As[lc+0][lr]=av.x; As[lc+1][lr]=av.y; As[lc+2][lr]=av.z; As[lc+3][lr]=av.w;
        Bs[lc+0][lr]=bv4.x; Bs[lc+1][lr]=bv4.y; Bs[lc+2][lr]=bv4.z; Bs[lc+3][lr]=bv4.w;
        __syncthreads();
#pragma unroll
        for (int kk=0; kk<16; kk++){
            float4 ra = *(const float4*)&As[kk][tr];
            float4 rb = *(const float4*)&Bs[kk][tc];
            acc[0][0]+=ra.x*rb.x; acc[0][1]+=ra.x*rb.y; acc[0][2]+=ra.x*rb.z; acc[0][3]+=ra.x*rb.w;
            acc[1][0]+=ra.y*rb.x; acc[1][1]+=ra.y*rb.y; acc[1][2]+=ra.y*rb.z; acc[1][3]+=ra.y*rb.w;
            acc[2][0]+=ra.z*rb.x; acc[2][1]+=ra.z*rb.y; acc[2][2]+=ra.z*rb.z; acc[2][3]+=ra.z*rb.w;
            acc[3][0]+=ra.w*rb.x; acc[3][1]+=ra.w*rb.y; acc[3][2]+=ra.w*rb.z; acc[3][3]+=ra.w*rb.w;
        }
        __syncthreads();
    }
#pragma unroll
    for (int i=0;i<4;i++)
#pragma unroll
        for (int j=0;j<4;j++)
            C[(size_t)(bm+tr+i)*DD + bn+tc+j] = acc[i][j] + bias[bn+tc+j];
}

// ---------------- output projection: g_att = g_oc @ Wo^T + bo ----------------
__global__ void oproj_kernel(const float* __restrict__ W,
                             const float* __restrict__ bias)
{
    __shared__ float As[16][68];
    __shared__ float Bs[16][68];
    const int tid = threadIdx.x;
    const int bm = blockIdx.x*64, bn = blockIdx.y*64;
    const int lr = tid>>2, lc = (tid&3)<<2;
    const int tr = (tid>>4)<<2, tc = (tid&15)<<2;
    const float* arow = g_oc + (size_t)(bm+lr)*DD;
    const float* brow = W + (size_t)(bn+lr)*DD;
    float acc[4][4] = {};
    for (int k0=0; k0<DD; k0+=16){
        float4 av = *(const float4*)(arow + k0 + lc);
        float4 bv4 = *(const float4*)(brow + k0 + lc);
        As[lc+0][lr]=av.x; As[lc+1][lr]=av.y; As[lc+2][lr]=av.z; As[lc+3][lr]=av.w;
        Bs[lc+0][lr]=bv4.x; Bs[lc+1][lr]=bv4.y; Bs[lc+2][lr]=bv4.z; Bs[lc+3][lr]=bv4.w;
        __syncthreads();
#pragma unroll
        for (int kk=0; kk<16; kk++){
            float4 ra = *(const float4*)&As[kk][tr];
            float4 rb = *(const float4*)&Bs[kk][tc];
            acc[0][0]+=ra.x*rb.x; acc[0][1]+=ra.x*rb.y; acc[0][2]+=ra.x*rb.z; acc[0][3]+=ra.x*rb.w;
            acc[1][0]+=ra.y*rb.x; acc[1][1]+=ra.y*rb.y; acc[1][2]+=ra.y*rb.z; acc[1][3]+=ra.y*rb.w;
            acc[2][0]+=ra.z*rb.x; acc[2][1]+=ra.z*rb.y; acc[2][2]+=ra.z*rb.z; acc[2][3]+=ra.z*rb.w;
            acc[3][0]+=ra.w*rb.x; acc[3][1]+=ra.w*rb.y; acc[3][2]+=ra.w*rb.z; acc[3][3]+=ra.w*rb.w;
        }
        __syncthreads();
    }
#pragma unroll
    for (int i=0;i<4;i++)
#pragma unroll
        for (int j=0;j<4;j++)
            g_att[(size_t)(bm+tr+i)*DD + bn+tc+j] = acc[i][j] + bias[bn+tc+j];
}

// ---------------- scores: S[bh,i,j] = (Q[b,i,h,:] . K[b,j,h,:]) / 8 ----------
__global__ void scores_kernel()
{
    __shared__ float As[16][68];
    __shared__ float Bs[16][68];
    const int bh = blockIdx.z, b = bh>>2, h = bh&3;
    const int bm = blockIdx.x*64, bn = blockIdx.y*64;
    const int tid = threadIdx.x;
    const int lr = tid>>2, lc = (tid&3)<<2;
    const int tr = (tid>>4)<<2, tc = (tid&15)<<2;
    const float* arow = g_q + ((size_t)(b*TT + bm + lr))*DD + h*HD;
    const float* brow = g_k + ((size_t)(b*TT + bn + lr))*DD + h*HD;
    float acc[4][4] = {};
    for (int k0=0; k0<HD; k0+=16){
        float4 av = *(const float4*)(arow + k0 + lc);
        float4 bv = *(const float4*)(brow + k0 + lc);
        As[lc+0][lr]=av.x; As[lc+1][lr]=av.y; As[lc+2][lr]=av.z; As[lc+3][lr]=av.w;
        Bs[lc+0][lr]=bv.x; Bs[lc+1][lr]=bv.y; Bs[lc+2][lr]=bv.z; Bs[lc+3][lr]=bv.w;
        __syncthreads();
#pragma unroll
        for (int kk=0; kk<16; kk++){
            float4 ra = *(const float4*)&As[kk][tr];
            float4 rb = *(const float4*)&Bs[kk][tc];
            acc[0][0]+=ra.x*rb.x; acc[0][1]+=ra.x*rb.y; acc[0][2]+=ra.x*rb.z; acc[0][3]+=ra.x*rb.w;
            acc[1][0]+=ra.y*rb.x; acc[1][1]+=ra.y*rb.y; acc[1][2]+=ra.y*rb.z; acc[1][3]+=ra.y*rb.w;
            acc[2][0]+=ra.z*rb.x; acc[2][1]+=ra.z*rb.y; acc[2][2]+=ra.z*rb.z; acc[2][3]+=ra.z*rb.w;
            acc[3][0]+=ra.w*rb.x; acc[3][1]+=ra.w*rb.y; acc[3][2]+=ra.w*rb.z; acc[3][3]+=ra.w*rb.w;
        }
        __syncthreads();
    }
#pragma unroll
    for (int i=0;i<4;i++)
#pragma unroll
        for (int j=0;j<4;j++)
            g_s[((size_t)bh*TT + bm+tr+i)*TT + bn+tc+j] = acc[i][j]*0.125f;
}

// ---------------- softmax over last dim (512), one warp per row -------------
__global__ void softmax_kernel()
{
    const int w = (blockIdx.x*blockDim.x + threadIdx.x) >> 5;
    const int lane = threadIdx.x & 31;
    float* row = g_s + (size_t)w*TT;
    float v[16];
#pragma unroll
    for (int q=0;q<16;q++) v[q] = row[lane + 32*q];
    float m = v[0];
#pragma unroll
    for (int q=1;q<16;q++) m = fmaxf(m, v[q]);
#pragma unroll
    for (int off=16; off; off>>=1) m = fmaxf(m, __shfl_xor_sync(0xffffffffu, m, off));
    float s = 0.f;
#pragma unroll
    for (int q=0;q<16;q++){ v[q] = __expf(v[q]-m); s += v[q]; }
#pragma unroll
    for (int off=16; off; off>>=1) s += __shfl_xor_sync(0xffffffffu, s, off);
    float inv = __fdividef(1.0f, s);
#pragma unroll
    for (int q=0;q<16;q++) row[lane + 32*q] = v[q]*inv;
}

// ---------------- O = P @ V  (per bh: 512x64, K=512) -------------------------
__global__ void pv_kernel()
{
    __shared__ float As[16][68];
    __shared__ float Bs[16][68];
    const int bh = blockIdx.z, b = bh>>2, h = bh&3;
    const int bm = blockIdx.x*64;
    const int tid = threadIdx.x;
    const int lr = tid>>2, lc = (tid&3)<<2;     // A tile load
    const int kr = tid>>4, nc = (tid&15)<<2;    // B tile load
    const int tr = (tid>>4)<<2, tc = (tid&15)<<2;
    const float* arow = g_s + ((size_t)bh*TT + bm + lr)*TT;
    float acc[4][4] = {};
    for (int k0=0; k0<TT; k0+=16){
        float4 av = *(const float4*)(arow + k0 + lc);
        float4 bv = *(const float4*)(g_v + ((size_t)(b*TT + k0 + kr))*DD + h*HD + nc);
        As[lc+0][lr]=av.x; As[lc+1][lr]=av.y; As[lc+2][lr]=av.z; As[lc+3][lr]=av.w;
        *(float4*)&Bs[kr][nc] = bv;
        __syncthreads();
#pragma unroll
        for (int kk=0; kk<16; kk++){
            float4 ra = *(const float4*)&As[kk][tr];
            float4 rb = *(const float4*)&Bs[kk][tc];
            acc[0][0]+=ra.x*rb.x; acc[0][1]+=ra.x*rb.y; acc[0][2]+=ra.x*rb.z; acc[0][3]+=ra.x*rb.w;
            acc[1][0]+=ra.y*rb.x; acc[1][1]+=ra.y*rb.y; acc[1][2]+=ra.y*rb.z; acc[1][3]+=ra.y*rb.w;
            acc[2][0]+=ra.z*rb.x; acc[2][1]+=ra.z*rb.y; acc[2][2]+=ra.z*rb.z; acc[2][3]+=ra.z*rb.w;
            acc[3][0]+=ra.w*rb.x; acc[3][1]+=ra.w*rb.y; acc[3][2]+=ra.w*rb.z; acc[3][3]+=ra.w*rb.w;
        }
        __syncthreads();
    }
#pragma unroll
    for (int i=0;i<4;i++)
#pragma unroll
        for (int j=0;j<4;j++)
            g_oc[((size_t)(b*TT + bm+tr+i))*DD + h*HD + tc+j] = acc[i][j];
}

// ---------------- xproj: per (b,t), 16 dots of attn_out row with gate weights
__global__ void xproj_kernel(const float* __restrict__ Wf, const float* __restrict__ Wi,
                             const float* __restrict__ Wg, const float* __restrict__ Wo2,
                             const float* __restrict__ bf, const float* __restrict__ thf,
                             const float* __restrict__ bi, const float* __restrict__ thi,
                             const float* __restrict__ bg, const float* __restrict__ thg,
                             const float* __restrict__ bo2, const float* __restrict__ tho)
{
    __shared__ float sW[16][256];
    __shared__ float sBT[16];
    const int tid = threadIdx.x;
    {
        const float* Ws[4] = {Wf, Wi, Wg, Wo2};
        for (int i=tid; i<16*256; i+=256){
            int r = i>>8, k = i&255;
            sW[r][k] = Ws[r>>2][(r&3)*260 + k];
        }
        if (tid < 16){
            const float* bs[4] = {bf, bi, bg, bo2};
            const float* ts[4] = {thf, thi, thg, tho};
            sBT[tid] = bs[tid>>2][tid&3] + ts[tid>>2][tid&3];
        }
    }
    __syncthreads();
    const int m = blockIdx.x*8 + (tid>>5);    // row over (b,t)
    const int lane = tid & 31;
    const float* arow = g_att + (size_t)m*256;
    float av[8];
#pragma unroll
    for (int q=0;q<8;q++) av[q] = arow[lane + 32*q];
    float myval = 0.f;
#pragma unroll
    for (int r=0; r<16; r++){
        float acc = 0.f;
#pragma unroll
        for (int q=0;q<8;q++) acc += av[q]*sW[r][lane + 32*q];
#pragma unroll
        for (int off=16; off; off>>=1) acc += __shfl_xor_sync(0xffffffffu, acc, off);
        if (lane == r) myval = acc;
    }
    if (lane < 16){
        int b = m>>9, t = m&511;
        g_xp[((size_t)t*BB + b)*16 + lane] = myval + sBT[lane];
    }
}

// ---------------- sequential LSTM scan: 4 lanes per batch, no barriers -------
// Quantum layer closed form: <Z0>=C1C2C3, <Z1>=C0C1, <Z2>=C0C1C2, <Z3>=C0C1C2C3
__global__ void lstm_kernel(const float* __restrict__ Wf, const float* __restrict__ Wi,
                            const float* __restrict__ Wg, const float* __restrict__ Wo2)
{
    const int lane = threadIdx.x;
    const int gate = lane & 3;
    const int bat  = blockIdx.x*8 + (lane>>2);
    const float* Wsel = (gate==0)?Wf:(gate==1)?Wi:(gate==2)?Wg:Wo2;
    float wh[4][4];
#pragma unroll
    for (int j=0;j<4;j++)
#pragma unroll
        for (int m2=0;m2<4;m2++)
            wh[j][m2] = Wsel[j*260 + 256 + m2];
    const bool isg = (gate==2);
    float cx0=0,cx1=0,cx2=0,cx3=0;
    float hx0=0,hx1=0,hx2=0,hx3=0;
    const float4* xpp = (const float4*)g_xp;
    float4 cur = xpp[(size_t)bat*4 + gate];
    const int gb = lane & ~3;
    for (int t=0; t<TT; t++){
        float4 nxt = cur;
        if (t+1 < TT) nxt = xpp[((size_t)(t+1)*BB + bat)*4 + gate];
        float a0 = cur.x + hx0*wh[0][0]+hx1*wh[0][1]+hx2*wh[0][2]+hx3*wh[0][3];
        float a1 = cur.y + hx0*wh[1][0]+hx1*wh[1][1]+hx2*wh[1][2]+hx3*wh[1][3];
        float a2 = cur.z + hx0*wh[2][0]+hx1*wh[2][1]+hx2*wh[2][2]+hx3*wh[2][3];
        float a3 = cur.w + hx0*wh[3][0]+hx1*wh[3][1]+hx2*wh[3][2]+hx3*wh[3][3];
        float C0=__cosf(a0), C1=__cosf(a1), C2=__cosf(a2), C3=__cosf(a3);
        float t12 = C1*C2;
        float z0 = t12*C3, z1 = C0*C1, z2 = C0*t12, z3 = z2*C3;
        float v0,v1,v2,v3;
        if (isg){ v0=ftanh(z0); v1=ftanh(z1); v2=ftanh(z2); v3=ftanh(z3); }
        else    { v0=fsig(z0);  v1=fsig(z1);  v2=fsig(z2);  v3=fsig(z3); }
        float f0=__shfl_sync(0xffffffffu,v0,gb+0), i0=__shfl_sync(0xffffffffu,v0,gb+1),
              q0=__shfl_sync(0xffffffffu,v0,gb+2), o0=__shfl_sync(0xffffffffu,v0,gb+3);
        float f1=__shfl_sync(0xffffffffu,v1,gb+0), i1=__shfl_sync(0xffffffffu,v1,gb+1),
              q1=__shfl_sync(0xffffffffu,v1,gb+2), o1=__shfl_sync(0xffffffffu,v1,gb+3);
        float f2=__shfl_sync(0xffffffffu,v2,gb+0), i2=__shfl_sync(0xffffffffu,v2,gb+1),
              q2=__shfl_sync(0xffffffffu,v2,gb+2), o2=__shfl_sync(0xffffffffu,v2,gb+3);
        float f3=__shfl_sync(0xffffffffu,v3,gb+0), i3=__shfl_sync(0xffffffffu,v3,gb+1),
              q3=__shfl_sync(0xffffffffu,v3,gb+2), o3=__shfl_sync(0xffffffffu,v3,gb+3);
        cx0 = f0*cx0 + i0*q0;  hx0 = o0*ftanh(cx0);
        cx1 = f1*cx1 + i1*q1;  hx1 = o1*ftanh(cx1);
        cx2 = f2*cx2 + i2*q2;  hx2 = o2*ftanh(cx2);
        cx3 = f3*cx3 + i3*q3;  hx3 = o3*ftanh(cx3);
        float outv = (gate==0)?hx0:(gate==1)?hx1:(gate==2)?hx2:hx3;
        g_hs[((size_t)bat*TT + t)*4 + gate] = outv;
        cur = nxt;
    }
}

// ---------------- logits + log_softmax: one warp per (b,t) -------------------
__global__ void logits_kernel(const float* __restrict__ Wt,
                              const float* __restrict__ bt,
                              float* __restrict__ out)
{
    const int w = (blockIdx.x*blockDim.x + threadIdx.x) >> 5;   // 0..8191
    const int lane = threadIdx.x & 31;
    float4 h = *(const float4*)(g_hs + (size_t)w*4);
    int j0 = lane, j1 = lane + 32;
    float l0 = bt[j0] + h.x*Wt[j0*4+0] + h.y*Wt[j0*4+1] + h.z*Wt[j0*4+2] + h.w*Wt[j0*4+3];
    float l1 = bt[j1] + h.x*Wt[j1*4+0] + h.y*Wt[j1*4+1] + h.z*Wt[j1*4+2] + h.w*Wt[j1*4+3];
    float m = fmaxf(l0, l1);
#pragma unroll
    for (int off=16; off; off>>=1) m = fmaxf(m, __shfl_xor_sync(0xffffffffu, m, off));
    float s = __expf(l0-m) + __expf(l1-m);
#pragma unroll
    for (int off=16; off; off>>=1) s += __shfl_xor_sync(0xffffffffu, s, off);
    float ls = __logf(s) + m;
    out[(size_t)w*64 + j0] = l0 - ls;
    out[(size_t)w*64 + j1] = l1 - ls;
}

// ---------------- launch ------------------------------------------------------
extern "C" void kernel_launch(void* const* d_in, const int* in_sizes, int n_in,
                              void* d_out, int out_size)
{
    (void)in_sizes; (void)n_in; (void)out_size;
    const int*   sentence = (const int*)  d_in[0];
    const float* emb = (const float*)d_in[1];
    const float* Wq  = (const float*)d_in[2];  const float* bq  = (const float*)d_in[3];
    const float* Wk  = (const float*)d_in[4];  const float* bk  = (const float*)d_in[5];
    const float* Wv  = (const float*)d_in[6];  const float* bv  = (const float*)d_in[7];
    const float* Wo  = (const float*)d_in[8];  const float* bo  = (const float*)d_in[9];
    const float* Wf  = (const float*)d_in[10]; const float* bf  = (const float*)d_in[11];
    const float* thf = (const float*)d_in[12];
    const float* Wi  = (const float*)d_in[13]; const float* bi  = (const float*)d_in[14];
    const float* thi = (const float*)d_in[15];
    const float* Wg  = (const float*)d_in[16]; const float* bg  = (const float*)d_in[17];
    const float* thg = (const float*)d_in[18];
    const float* Wo2 = (const float*)d_in[19]; const float* bo2 = (const float*)d_in[20];
    const float* tho = (const float*)d_in[21];
    const float* Wt  = (const float*)d_in[22]; const float* bt  = (const float*)d_in[23];
    float* out = (float*)d_out;

    qkv_kernel<<<dim3(128, 4, 3), 256>>>(emb, sentence, Wq, bq, Wk, bk, Wv, bv);
    scores_kernel<<<dim3(8,8,64), 256>>>();
    softmax_kernel<<<4096, 256>>>();
    pv_kernel<<<dim3(8,1,64), 256>>>();
    oproj_kernel<<<dim3(128, 4), 256>>>(Wo, bo);
    xproj_kernel<<<1024, 256>>>(Wf,Wi,Wg,Wo2, bf,thf, bi,thi, bg,thg, bo2,tho);
    lstm_kernel<<<2, 32>>>(Wf, Wi, Wg, Wo2);
    logits_kernel<<<1024, 256>>>(Wt, bt, out);
}

// round 10
// speedup vs baseline: 1.0203x; 1.0203x over previous
#include <cuda_runtime.h>
#include <cstddef>

#define BB 16
#define TT 512
#define DD 256
#define HH 4
#define HD 64
#define MM (BB*TT)          // 8192

// ---------------- scratch (static device memory; no allocs) ----------------
__device__ float g_q[MM*DD];
__device__ float g_k[MM*DD];
__device__ float g_v[MM*DD];
__device__ float g_oc[MM*DD];
__device__ float g_att[MM*DD];
__device__ float g_s[(size_t)BB*HH*TT*TT];   // 64 MB attention scores
__device__ float g_xp[TT*BB*16];             // per-step gate pre-activations
__device__ float g_hs[BB*TT*4];              // lstm hidden outputs

__device__ __forceinline__ float fsig(float x){
    float e = __expf(-x);
    return __fdividef(1.0f, 1.0f + e);
}
__device__ __forceinline__ float ftanh(float x){
    float e = __expf(2.0f*x);
    return __fdividef(e - 1.0f, e + 1.0f);
}

// ============================================================================
// 128x128-tile SGEMM with 8x8 per-thread microkernel, BK=8, double-buffered.
// C[M,N] = A[M,K] @ W[N,K]^T + bias.  256 threads: ty=tid/16 (8 rows*?) ...
// thread (ty,tx) computes C[bm+ty*8 .. +7][bn+tx*8 .. +7].
// ============================================================================

// ---- fused QKV projection + output projection --------------------------------
// sel 0/1/2: A = emb[idx[.]] (gather), C = g_q/g_k/g_v
// sel 3    : A = g_oc,                 C = g_att
__global__ __launch_bounds__(256, 2)
void proj128_kernel(const float* __restrict__ emb,
                    const int*   __restrict__ idx,
                    const float* __restrict__ Wq, const float* __restrict__ bq,
                    const float* __restrict__ Wk, const float* __restrict__ bk,
                    const float* __restrict__ Wv, const float* __restrict__ bv,
                    int sel_base)
{
    __shared__ float As[2][8][128];
    __shared__ float Bs[2][8][128];
    const int sel = sel_base + blockIdx.z;
    const float* W    = (sel==0)?Wq:(sel==1)?Wk:(sel==2)?Wv:Wq;   // sel3 passes Wo in Wq slot
    const float* bias = (sel==0)?bq:(sel==1)?bk:(sel==2)?bv:bq;
    float* C          = (sel==0)?g_q:(sel==1)?g_k:(sel==2)?g_v:g_att;
    const int tid = threadIdx.x;
    const int bm = blockIdx.x*128, bn = blockIdx.y*128;
    const int ty = tid>>4, tx = tid&15;
    const int lrow = tid>>1, lkc = (tid&1)<<2;   // loader: row 0..127, k-chunk 0/4

    const float* arow;
    if (sel < 3) arow = emb + (size_t)idx[bm+lrow]*DD + lkc;
    else         arow = g_oc + (size_t)(bm+lrow)*DD + lkc;
    const float* brow = W + (size_t)(bn+lrow)*DD + lkc;

    float acc[8][8] = {};
    float4 av = *(const float4*)(arow);
    float4 bv4 = *(const float4*)(brow);
    As[0][lkc+0][lrow]=av.x; As[0][lkc+1][lrow]=av.y; As[0][lkc+2][lrow]=av.z; As[0][lkc+3][lrow]=av.w;
    Bs[0][lkc+0][lrow]=bv4.x; Bs[0][lkc+1][lrow]=bv4.y; Bs[0][lkc+2][lrow]=bv4.z; Bs[0][lkc+3][lrow]=bv4.w;
    __syncthreads();

    const int NT = DD/8;   // 32
    for (int kt=0; kt<NT; kt++){
        int buf = kt & 1;
        if (kt+1 < NT){
            av  = *(const float4*)(arow + (kt+1)*8);
            bv4 = *(const float4*)(brow + (kt+1)*8);
        }
#pragma unroll
        for (int k=0;k<8;k++){
            float4 a0 = *(const float4*)&As[buf][k][ty*8];
            float4 a1 = *(const float4*)&As[buf][k][ty*8+4];
            float4 b0 = *(const float4*)&Bs[buf][k][tx*8];
            float4 b1 = *(const float4*)&Bs[buf][k][tx*8+4];
            float ar[8] = {a0.x,a0.y,a0.z,a0.w,a1.x,a1.y,a1.z,a1.w};
            float br[8] = {b0.x,b0.y,b0.z,b0.w,b1.x,b1.y,b1.z,b1.w};
#pragma unroll
            for (int i=0;i<8;i++)
#pragma unroll
                for (int j=0;j<8;j++)
                    acc[i][j] += ar[i]*br[j];
        }
        if (kt+1 < NT){
            int nb = (kt+1)&1;
            As[nb][lkc+0][lrow]=av.x; As[nb][lkc+1][lrow]=av.y; As[nb][lkc+2][lrow]=av.z; As[nb][lkc+3][lrow]=av.w;
            Bs[nb][lkc+0][lrow]=bv4.x; Bs[nb][lkc+1][lrow]=bv4.y; Bs[nb][lkc+2][lrow]=bv4.z; Bs[nb][lkc+3][lrow]=bv4.w;
            __syncthreads();
        }
    }
#pragma unroll
    for (int i=0;i<8;i++){
        float* crow = C + (size_t)(bm+ty*8+i)*DD + bn + tx*8;
        const float* bp = bias + bn + tx*8;
        float4 o0 = {acc[i][0]+bp[0], acc[i][1]+bp[1], acc[i][2]+bp[2], acc[i][3]+bp[3]};
        float4 o1 = {acc[i][4]+bp[4], acc[i][5]+bp[5], acc[i][6]+bp[6], acc[i][7]+bp[7]};
        *(float4*)crow = o0;
        *(float4*)(crow+4) = o1;
    }
}

// ---- scores: S[bh,i,j] = (Q[b,i,h,:].K[b,j,h,:])/8,  128x128 tile, K=64 ----
__global__ __launch_bounds__(256, 2)
void scores128_kernel()
{
    __shared__ float As[2][8][128];
    __shared__ float Bs[2][8][128];
    const int bh = blockIdx.z, b = bh>>2, h = bh&3;
    const int bm = blockIdx.x*128, bn = blockIdx.y*128;
    const int tid = threadIdx.x;
    const int ty = tid>>4, tx = tid&15;
    const int lrow = tid>>1, lkc = (tid&1)<<2;

    const float* arow = g_q + ((size_t)(b*TT + bm + lrow))*DD + h*HD + lkc;
    const float* brow = g_k + ((size_t)(b*TT + bn + lrow))*DD + h*HD + lkc;

    float acc[8][8] = {};
    float4 av = *(const float4*)(arow);
    float4 bv4 = *(const float4*)(brow);
    As[0][lkc+0][lrow]=av.x; As[0][lkc+1][lrow]=av.y; As[0][lkc+2][lrow]=av.z; As[0][lkc+3][lrow]=av.w;
    Bs[0][lkc+0][lrow]=bv4.x; Bs[0][lkc+1][lrow]=bv4.y; Bs[0][lkc+2][lrow]=bv4.z; Bs[0][lkc+3][lrow]=bv4.w;
    __syncthreads();

    const int NT = HD/8;   // 8
    for (int kt=0; kt<NT; kt++){
        int buf = kt & 1;
        if (kt+1 < NT){
            av  = *(const float4*)(arow + (kt+1)*8);
            bv4 = *(const float4*)(brow + (kt+1)*8);
        }
#pragma unroll
        for (int k=0;k<8;k++){
            float4 a0 = *(const float4*)&As[buf][k][ty*8];
            float4 a1 = *(const float4*)&As[buf][k][ty*8+4];
            float4 b0 = *(const float4*)&Bs[buf][k][tx*8];
            float4 b1 = *(const float4*)&Bs[buf][k][tx*8+4];
            float ar[8] = {a0.x,a0.y,a0.z,a0.w,a1.x,a1.y,a1.z,a1.w};
            float br[8] = {b0.x,b0.y,b0.z,b0.w,b1.x,b1.y,b1.z,b1.w};
#pragma unroll
            for (int i=0;i<8;i++)
#pragma unroll
                for (int j=0;j<8;j++)
                    acc[i][j] += ar[i]*br[j];
        }
        if (kt+1 < NT){
            int nb = (kt+1)&1;
            As[nb][lkc+0][lrow]=av.x; As[nb][lkc+1][lrow]=av.y; As[nb][lkc+2][lrow]=av.z; As[nb][lkc+3][lrow]=av.w;
            Bs[nb][lkc+0][lrow]=bv4.x; Bs[nb][lkc+1][lrow]=bv4.y; Bs[nb][lkc+2][lrow]=bv4.z; Bs[nb][lkc+3][lrow]=bv4.w;
            __syncthreads();
        }
    }
#pragma unroll
    for (int i=0;i<8;i++){
        float* crow = g_s + ((size_t)bh*TT + bm+ty*8+i)*TT + bn + tx*8;
        float4 o0 = {acc[i][0]*0.125f, acc[i][1]*0.125f, acc[i][2]*0.125f, acc[i][3]*0.125f};
        float4 o1 = {acc[i][4]*0.125f, acc[i][5]*0.125f, acc[i][6]*0.125f, acc[i][7]*0.125f};
        *(float4*)crow = o0;
        *(float4*)(crow+4) = o1;
    }
}

// ---------------- softmax over last dim (512), one warp per row -------------
__global__ void softmax_kernel()
{
    const int w = (blockIdx.x*blockDim.x + threadIdx.x) >> 5;
    const int lane = threadIdx.x & 31;
    float* row = g_s + (size_t)w*TT;
    float v[16];
#pragma unroll
    for (int q=0;q<16;q++) v[q] = row[lane + 32*q];
    float m = v[0];
#pragma unroll
    for (int q=1;q<16;q++) m = fmaxf(m, v[q]);
#pragma unroll
    for (int off=16; off; off>>=1) m = fmaxf(m, __shfl_xor_sync(0xffffffffu, m, off));
    float s = 0.f;
#pragma unroll
    for (int q=0;q<16;q++){ v[q] = __expf(v[q]-m); s += v[q]; }
#pragma unroll
    for (int off=16; off; off>>=1) s += __shfl_xor_sync(0xffffffffu, s, off);
    float inv = __fdividef(1.0f, s);
#pragma unroll
    for (int q=0;q<16;q++) row[lane + 32*q] = v[q]*inv;
}

// ---- O = P @ V : per bh, M=512, N=64, K=512.  Tile 128x64, 8x4/thread ------
__global__ __launch_bounds__(256, 2)
void pv128_kernel()
{
    __shared__ float As[2][8][128];
    __shared__ float Bs[2][8][64];
    const int bh = blockIdx.y, b = bh>>2, h = bh&3;
    const int bm = blockIdx.x*128;
    const int tid = threadIdx.x;
    const int ty = tid>>4, tx = tid&15;          // 8 rows x 4 cols per thread
    const int lrow = tid>>1, lkc = (tid&1)<<2;   // A loader
    const int vrow = tid>>4, vcol = (tid&15)<<2; // B loader (threads 0..127)

    const float* arow = g_s + ((size_t)bh*TT + bm + lrow)*TT + lkc;
    const float* vbase = g_v + ((size_t)(b*TT))*DD + h*HD + vcol;

    float acc[8][4] = {};
    float4 av = *(const float4*)(arow);
    float4 bv4;
    bool bload = (tid < 128);
    if (bload) bv4 = *(const float4*)(vbase + (size_t)vrow*DD);
    As[0][lkc+0][lrow]=av.x; As[0][lkc+1][lrow]=av.y; As[0][lkc+2][lrow]=av.z; As[0][lkc+3][lrow]=av.w;
    if (bload) *(float4*)&Bs[0][vrow][vcol] = bv4;
    __syncthreads();

    const int NT = TT/8;   // 64
    for (int kt=0; kt<NT; kt++){
        int buf = kt & 1;
        if (kt+1 < NT){
            av = *(const float4*)(arow + (kt+1)*8);
            if (bload) bv4 = *(const float4*)(vbase + (size_t)((kt+1)*8 + vrow)*DD);
        }
#pragma unroll
        for (int k=0;k<8;k++){
            float4 a0 = *(const float4*)&As[buf][k][ty*8];
            float4 a1 = *(const float4*)&As[buf][k][ty*8+4];
            float4 b0 = *(const float4*)&Bs[buf][k][tx*4];
            float ar[8] = {a0.x,a0.y,a0.z,a0.w,a1.x,a1.y,a1.z,a1.w};
#pragma unroll
            for (int i=0;i<8;i++){
                acc[i][0] += ar[i]*b0.x;
                acc[i][1] += ar[i]*b0.y;
                acc[i][2] += ar[i]*b0.z;
                acc[i][3] += ar[i]*b0.w;
            }
        }
        if (kt+1 < NT){
            int nb = (kt+1)&1;
            As[nb][lkc+0][lrow]=av.x; As[nb][lkc+1][lrow]=av.y; As[nb][lkc+2][lrow]=av.z; As[nb][lkc+3][lrow]=av.w;
            if (bload) *(float4*)&Bs[nb][vrow][vcol] = bv4;
            __syncthreads();
        }
    }
#pragma unroll
    for (int i=0;i<8;i++){
        float* crow = g_oc + ((size_t)(b*TT + bm+ty*8+i))*DD + h*HD + tx*4;
        float4 o = {acc[i][0], acc[i][1], acc[i][2], acc[i][3]};
        *(float4*)crow = o;
    }
}

// ---------------- xproj: per (b,t), 16 dots of attn_out row with gate weights
__global__ void xproj_kernel(const float* __restrict__ Wf, const float* __restrict__ Wi,
                             const float* __restrict__ Wg, const float* __restrict__ Wo2,
                             const float* __restrict__ bf, const float* __restrict__ thf,
                             const float* __restrict__ bi, const float* __restrict__ thi,
                             const float* __restrict__ bg, const float* __restrict__ thg,
                             const float* __restrict__ bo2, const float* __restrict__ tho)
{
    __shared__ float sW[16][256];
    __shared__ float sBT[16];
    const int tid = threadIdx.x;
    {
        const float* Ws[4] = {Wf, Wi, Wg, Wo2};
        for (int i=tid; i<16*256; i+=256){
            int r = i>>8, k = i&255;
            sW[r][k] = Ws[r>>2][(r&3)*260 + k];
        }
        if (tid < 16){
            const float* bs[4] = {bf, bi, bg, bo2};
            const float* ts[4] = {thf, thi, thg, tho};
            sBT[tid] = bs[tid>>2][tid&3] + ts[tid>>2][tid&3];
        }
    }
    __syncthreads();
    const int m = blockIdx.x*8 + (tid>>5);    // row over (b,t)
    const int lane = tid & 31;
    const float* arow = g_att + (size_t)m*256;
    float av[8];
#pragma unroll
    for (int q=0;q<8;q++) av[q] = arow[lane + 32*q];
    float myval = 0.f;
#pragma unroll
    for (int r=0; r<16; r++){
        float acc = 0.f;
#pragma unroll
        for (int q=0;q<8;q++) acc += av[q]*sW[r][lane + 32*q];
#pragma unroll
        for (int off=16; off; off>>=1) acc += __shfl_xor_sync(0xffffffffu, acc, off);
        if (lane == r) myval = acc;
    }
    if (lane < 16){
        int b = m>>9, t = m&511;
        g_xp[((size_t)t*BB + b)*16 + lane] = myval + sBT[lane];
    }
}

// ---------------- sequential LSTM scan: 4 lanes per batch, no barriers -------
// Quantum layer closed form: <Z0>=C1C2C3, <Z1>=C0C1, <Z2>=C0C1C2, <Z3>=C0C1C2C3
__global__ void lstm_kernel(const float* __restrict__ Wf, const float* __restrict__ Wi,
                            const float* __restrict__ Wg, const float* __restrict__ Wo2)
{
    const int lane = threadIdx.x;
    const int gate = lane & 3;
    const int bat  = blockIdx.x*8 + (lane>>2);
    const float* Wsel = (gate==0)?Wf:(gate==1)?Wi:(gate==2)?Wg:Wo2;
    float wh[4][4];
#pragma unroll
    for (int j=0;j<4;j++)
#pragma unroll
        for (int m2=0;m2<4;m2++)
            wh[j][m2] = Wsel[j*260 + 256 + m2];
    const bool isg = (gate==2);
    float cx0=0,cx1=0,cx2=0,cx3=0;
    float hx0=0,hx1=0,hx2=0,hx3=0;
    const float4* xpp = (const float4*)g_xp;
    float4 cur = xpp[(size_t)bat*4 + gate];
    const int gb = lane & ~3;
    for (int t=0; t<TT; t++){
        float4 nxt = cur;
        if (t+1 < TT) nxt = xpp[((size_t)(t+1)*BB + bat)*4 + gate];
        float a0 = cur.x + hx0*wh[0][0]+hx1*wh[0][1]+hx2*wh[0][2]+hx3*wh[0][3];
        float a1 = cur.y + hx0*wh[1][0]+hx1*wh[1][1]+hx2*wh[1][2]+hx3*wh[1][3];
        float a2 = cur.z + hx0*wh[2][0]+hx1*wh[2][1]+hx2*wh[2][2]+hx3*wh[2][3];
        float a3 = cur.w + hx0*wh[3][0]+hx1*wh[3][1]+hx2*wh[3][2]+hx3*wh[3][3];
        float C0=__cosf(a0), C1=__cosf(a1), C2=__cosf(a2), C3=__cosf(a3);
        float t12 = C1*C2;
        float z0 = t12*C3, z1 = C0*C1, z2 = C0*t12, z3 = z2*C3;
        float v0,v1,v2,v3;
        if (isg){ v0=ftanh(z0); v1=ftanh(z1); v2=ftanh(z2); v3=ftanh(z3); }
        else    { v0=fsig(z0);  v1=fsig(z1);  v2=fsig(z2);  v3=fsig(z3); }
        float f0=__shfl_sync(0xffffffffu,v0,gb+0), i0=__shfl_sync(0xffffffffu,v0,gb+1),
              q0=__shfl_sync(0xffffffffu,v0,gb+2), o0=__shfl_sync(0xffffffffu,v0,gb+3);
        float f1=__shfl_sync(0xffffffffu,v1,gb+0), i1=__shfl_sync(0xffffffffu,v1,gb+1),
              q1=__shfl_sync(0xffffffffu,v1,gb+2), o1=__shfl_sync(0xffffffffu,v1,gb+3);
        float f2=__shfl_sync(0xffffffffu,v2,gb+0), i2=__shfl_sync(0xffffffffu,v2,gb+1),
              q2=__shfl_sync(0xffffffffu,v2,gb+2), o2=__shfl_sync(0xffffffffu,v2,gb+3);
        float f3=__shfl_sync(0xffffffffu,v3,gb+0), i3=__shfl_sync(0xffffffffu,v3,gb+1),
              q3=__shfl_sync(0xffffffffu,v3,gb+2), o3=__shfl_sync(0xffffffffu,v3,gb+3);
        cx0 = f0*cx0 + i0*q0;  hx0 = o0*ftanh(cx0);
        cx1 = f1*cx1 + i1*q1;  hx1 = o1*ftanh(cx1);
        cx2 = f2*cx2 + i2*q2;  hx2 = o2*ftanh(cx2);
        cx3 = f3*cx3 + i3*q3;  hx3 = o3*ftanh(cx3);
        float outv = (gate==0)?hx0:(gate==1)?hx1:(gate==2)?hx2:hx3;
        g_hs[((size_t)bat*TT + t)*4 + gate] = outv;
        cur = nxt;
    }
}

// ---------------- logits + log_softmax: one warp per (b,t) -------------------
__global__ void logits_kernel(const float* __restrict__ Wt,
                              const float* __restrict__ bt,
                              float* __restrict__ out)
{
    const int w = (blockIdx.x*blockDim.x + threadIdx.x) >> 5;   // 0..8191
    const int lane = threadIdx.x & 31;
    float4 h = *(const float4*)(g_hs + (size_t)w*4);
    int j0 = lane, j1 = lane + 32;
    float l0 = bt[j0] + h.x*Wt[j0*4+0] + h.y*Wt[j0*4+1] + h.z*Wt[j0*4+2] + h.w*Wt[j0*4+3];
    float l1 = bt[j1] + h.x*Wt[j1*4+0] + h.y*Wt[j1*4+1] + h.z*Wt[j1*4+2] + h.w*Wt[j1*4+3];
    float m = fmaxf(l0, l1);
#pragma unroll
    for (int off=16; off; off>>=1) m = fmaxf(m, __shfl_xor_sync(0xffffffffu, m, off));
    float s = __expf(l0-m) + __expf(l1-m);
#pragma unroll
    for (int off=16; off; off>>=1) s += __shfl_xor_sync(0xffffffffu, s, off);
    float ls = __logf(s) + m;
    out[(size_t)w*64 + j0] = l0 - ls;
    out[(size_t)w*64 + j1] = l1 - ls;
}

// ---------------- launch ------------------------------------------------------
extern "C" void kernel_launch(void* const* d_in, const int* in_sizes, int n_in,
                              void* d_out, int out_size)
{
    (void)in_sizes; (void)n_in; (void)out_size;
    const int*   sentence = (const int*)  d_in[0];
    const float* emb = (const float*)d_in[1];
    const float* Wq  = (const float*)d_in[2];  const float* bq  = (const float*)d_in[3];
    const float* Wk  = (const float*)d_in[4];  const float* bk  = (const float*)d_in[5];
    const float* Wv  = (const float*)d_in[6];  const float* bv  = (const float*)d_in[7];
    const float* Wo  = (const float*)d_in[8];  const float* bo  = (const float*)d_in[9];
    const float* Wf  = (const float*)d_in[10]; const float* bf  = (const float*)d_in[11];
    const float* thf = (const float*)d_in[12];
    const float* Wi  = (const float*)d_in[13]; const float* bi  = (const float*)d_in[14];
    const float* thi = (const float*)d_in[15];
    const float* Wg  = (const float*)d_in[16]; const float* bg  = (const float*)d_in[17];
    const float* thg = (const float*)d_in[18];
    const float* Wo2 = (const float*)d_in[19]; const float* bo2 = (const float*)d_in[20];
    const float* tho = (const float*)d_in[21];
    const float* Wt  = (const float*)d_in[22]; const float* bt  = (const float*)d_in[23];
    float* out = (float*)d_out;

    // QKV: grid (M/128=64, N/128=2, 3)
    proj128_kernel<<<dim3(64, 2, 3), 256>>>(emb, sentence, Wq, bq, Wk, bk, Wv, bv, 0);
    scores128_kernel<<<dim3(4, 4, 64), 256>>>();
    softmax_kernel<<<4096, 256>>>();
    pv128_kernel<<<dim3(4, 64), 256>>>();
    // O-projection: sel=3, A=g_oc, W=Wo passed in Wq slot
    proj128_kernel<<<dim3(64, 2, 1), 256>>>(emb, sentence, Wo, bo, Wk, bk, Wv, bv, 3);
    xproj_kernel<<<1024, 256>>>(Wf,Wi,Wg,Wo2, bf,thf, bi,thi, bg,thg, bo2,tho);
    lstm_kernel<<<2, 32>>>(Wf, Wi, Wg, Wo2);
    logits_kernel<<<1024, 256>>>(Wt, bt, out);
}

// round 13
// speedup vs baseline: 1.1262x; 1.1037x over previous
#include <cuda_runtime.h>
#include <cstddef>

#define BB 16
#define TT 512
#define DD 256
#define HH 4
#define HD 64
#define MM (BB*TT)          // 8192

// ---------------- scratch (static device memory; no allocs) ----------------
__device__ float g_q[MM*DD];
__device__ float g_k[MM*DD];
__device__ float g_v[MM*DD];
__device__ float g_oc[MM*DD];
__device__ float g_att[MM*DD];
__device__ float g_xp[TT*BB*16];             // per-step gate pre-activations
__device__ float g_hs[BB*TT*4];              // lstm hidden outputs

__device__ __forceinline__ float fsig(float x){
    float e = __expf(-x);
    return __fdividef(1.0f, 1.0f + e);
}
__device__ __forceinline__ float ftanh(float x){
    float e = __expf(2.0f*x);
    return __fdividef(e - 1.0f, e + 1.0f);
}

// ============================================================================
// 128x128-tile SGEMM with 8x8 per-thread microkernel, BK=8, double-buffered.
// ============================================================================
// sel 0/1/2: A = emb[idx[.]] (gather), C = g_q/g_k/g_v
// sel 3    : A = g_oc,                 C = g_att
__global__ __launch_bounds__(256, 2)
void proj128_kernel(const float* __restrict__ emb,
                    const int*   __restrict__ idx,
                    const float* __restrict__ Wq, const float* __restrict__ bq,
                    const float* __restrict__ Wk, const float* __restrict__ bk,
                    const float* __restrict__ Wv, const float* __restrict__ bv,
                    int sel_base)
{
    __shared__ float As[2][8][128];
    __shared__ float Bs[2][8][128];
    const int sel = sel_base + blockIdx.z;
    const float* W    = (sel==0)?Wq:(sel==1)?Wk:(sel==2)?Wv:Wq;   // sel3 passes Wo in Wq slot
    const float* bias = (sel==0)?bq:(sel==1)?bk:(sel==2)?bv:bq;
    float* C          = (sel==0)?g_q:(sel==1)?g_k:(sel==2)?g_v:g_att;
    const int tid = threadIdx.x;
    const int bm = blockIdx.x*128, bn = blockIdx.y*128;
    const int ty = tid>>4, tx = tid&15;
    const int lrow = tid>>1, lkc = (tid&1)<<2;   // loader: row 0..127, k-chunk 0/4

    const float* arow;
    if (sel < 3) arow = emb + (size_t)idx[bm+lrow]*DD + lkc;
    else         arow = g_oc + (size_t)(bm+lrow)*DD + lkc;
    const float* brow = W + (size_t)(bn+lrow)*DD + lkc;

    float acc[8][8] = {};
    float4 av = *(const float4*)(arow);
    float4 bv4 = *(const float4*)(brow);
    As[0][lkc+0][lrow]=av.x; As[0][lkc+1][lrow]=av.y; As[0][lkc+2][lrow]=av.z; As[0][lkc+3][lrow]=av.w;
    Bs[0][lkc+0][lrow]=bv4.x; Bs[0][lkc+1][lrow]=bv4.y; Bs[0][lkc+2][lrow]=bv4.z; Bs[0][lkc+3][lrow]=bv4.w;
    __syncthreads();

    const int NT = DD/8;   // 32
    for (int kt=0; kt<NT; kt++){
        int buf = kt & 1;
        if (kt+1 < NT){
            av  = *(const float4*)(arow + (kt+1)*8);
            bv4 = *(const float4*)(brow + (kt+1)*8);
        }
#pragma unroll
        for (int k=0;k<8;k++){
            float4 a0 = *(const float4*)&As[buf][k][ty*8];
            float4 a1 = *(const float4*)&As[buf][k][ty*8+4];
            float4 b0 = *(const float4*)&Bs[buf][k][tx*8];
            float4 b1 = *(const float4*)&Bs[buf][k][tx*8+4];
            float ar[8] = {a0.x,a0.y,a0.z,a0.w,a1.x,a1.y,a1.z,a1.w};
            float br[8] = {b0.x,b0.y,b0.z,b0.w,b1.x,b1.y,b1.z,b1.w};
#pragma unroll
            for (int i=0;i<8;i++)
#pragma unroll
                for (int j=0;j<8;j++)
                    acc[i][j] += ar[i]*br[j];
        }
        if (kt+1 < NT){
            int nb = (kt+1)&1;
            As[nb][lkc+0][lrow]=av.x; As[nb][lkc+1][lrow]=av.y; As[nb][lkc+2][lrow]=av.z; As[nb][lkc+3][lrow]=av.w;
            Bs[nb][lkc+0][lrow]=bv4.x; Bs[nb][lkc+1][lrow]=bv4.y; Bs[nb][lkc+2][lrow]=bv4.z; Bs[nb][lkc+3][lrow]=bv4.w;
            __syncthreads();
        }
    }
#pragma unroll
    for (int i=0;i<8;i++){
        float* crow = C + (size_t)(bm+ty*8+i)*DD + bn + tx*8;
        const float* bp = bias + bn + tx*8;
        float4 o0 = {acc[i][0]+bp[0], acc[i][1]+bp[1], acc[i][2]+bp[2], acc[i][3]+bp[3]};
        float4 o1 = {acc[i][4]+bp[4], acc[i][5]+bp[5], acc[i][6]+bp[6], acc[i][7]+bp[7]};
        *(float4*)crow = o0;
        *(float4*)(crow+4) = o1;
    }
}

// ============================================================================
// Fused flash attention: scores + softmax + PV in one kernel.
// grid (4 m-chunks of 128 rows, 64 bh), 256 threads.
// Online softmax over KV tiles of 64 rows. Writes g_oc directly.
// Thread (ty=tid>>4, tx=tid&15) owns rows ty*8..+7, cols tx*4..+3.
// ============================================================================
#define PPAD 68   // sP row stride (floats); 68*4=272 B, 16B-aligned

__global__ __launch_bounds__(256, 2)
void flash_kernel()
{
    extern __shared__ float sm[];
    float* sQt = sm;                     // [64][128]  (k-major Q^T)   32 KB
    float* sKt = sm + 64*128;            // [64][64]   (k-major K^T)   16 KB
    float* sV  = sKt + 64*64;            // [64][64]   (kv-major V)    16 KB
    float* sP  = sV + 64*64;             // [128][PPAD] (row-major P)  34 KB

    const int bh = blockIdx.y, b = bh>>2, h = bh&3;
    const int bm = blockIdx.x*128;
    const int tid = threadIdx.x;
    const int ty = tid>>4, tx = tid&15;

    // ---- load Q chunk transposed (once) ----
    {
        int r = tid>>1, d0 = (tid&1)*32;
        const float* src = g_q + ((size_t)(b*TT + bm + r))*DD + h*HD + d0;
#pragma unroll
        for (int j=0;j<32;j+=4){
            float4 v = *(const float4*)(src + j);
            sQt[(d0+j+0)*128 + r] = v.x;
            sQt[(d0+j+1)*128 + r] = v.y;
            sQt[(d0+j+2)*128 + r] = v.z;
            sQt[(d0+j+3)*128 + r] = v.w;
        }
    }

    float accO[8][4] = {};
    float mrow[8], lrow[8];
#pragma unroll
    for (int i=0;i<8;i++){ mrow[i] = -1e30f; lrow[i] = 0.f; }

    for (int n0=0; n0<TT; n0+=64){
        __syncthreads();   // previous GEMM2 done reading sKt/sV/sP
        // ---- load K tile transposed + V tile natural ----
        {
            int n = tid>>2, d0 = (tid&3)*16;
            const float* ksrc = g_k + ((size_t)(b*TT + n0 + n))*DD + h*HD + d0;
            const float* vsrc = g_v + ((size_t)(b*TT + n0 + n))*DD + h*HD + d0;
#pragma unroll
            for (int j=0;j<16;j+=4){
                float4 v = *(const float4*)(ksrc + j);
                sKt[(d0+j+0)*64 + n] = v.x;
                sKt[(d0+j+1)*64 + n] = v.y;
                sKt[(d0+j+2)*64 + n] = v.z;
                sKt[(d0+j+3)*64 + n] = v.w;
                *(float4*)&sV[n*64 + d0 + j] = *(const float4*)(vsrc + j);
            }
        }
        __syncthreads();

        // ---- GEMM1: S[8][4] = Q chunk . K tile^T ----
        float s[8][4] = {};
#pragma unroll
        for (int k=0;k<64;k++){
            float4 a0 = *(const float4*)&sQt[k*128 + ty*8];
            float4 a1 = *(const float4*)&sQt[k*128 + ty*8 + 4];
            float4 b0 = *(const float4*)&sKt[k*64 + tx*4];
            float ar[8]={a0.x,a0.y,a0.z,a0.w,a1.x,a1.y,a1.z,a1.w};
#pragma unroll
            for (int i=0;i<8;i++){
                s[i][0]+=ar[i]*b0.x; s[i][1]+=ar[i]*b0.y;
                s[i][2]+=ar[i]*b0.z; s[i][3]+=ar[i]*b0.w;
            }
        }

        // ---- online softmax (rows span 16 tx lanes; width-16 shuffles) ----
#pragma unroll
        for (int i=0;i<8;i++){
            float s0=s[i][0]*0.125f, s1=s[i][1]*0.125f, s2=s[i][2]*0.125f, s3=s[i][3]*0.125f;
            float tm = fmaxf(fmaxf(s0,s1), fmaxf(s2,s3));
#pragma unroll
            for (int off=1; off<16; off<<=1)
                tm = fmaxf(tm, __shfl_xor_sync(0xffffffffu, tm, off, 16));
            float newm = fmaxf(mrow[i], tm);
            float corr = __expf(mrow[i] - newm);
            mrow[i] = newm;
            float p0=__expf(s0-newm), p1=__expf(s1-newm),
                  p2=__expf(s2-newm), p3=__expf(s3-newm);
            float ls = p0+p1+p2+p3;
#pragma unroll
            for (int off=1; off<16; off<<=1)
                ls += __shfl_xor_sync(0xffffffffu, ls, off, 16);
            lrow[i] = lrow[i]*corr + ls;
            accO[i][0]*=corr; accO[i][1]*=corr; accO[i][2]*=corr; accO[i][3]*=corr;
            float4 pv = {p0,p1,p2,p3};
            *(float4*)&sP[(ty*8+i)*PPAD + tx*4] = pv;
        }
        __syncthreads();

        // ---- GEMM2: accO += P . V  (contraction over 64 kv, 4 at a time) ----
#pragma unroll
        for (int kv0=0;kv0<64;kv0+=4){
            float4 br0 = *(const float4*)&sV[(kv0+0)*64 + tx*4];
            float4 br1 = *(const float4*)&sV[(kv0+1)*64 + tx*4];
            float4 br2 = *(const float4*)&sV[(kv0+2)*64 + tx*4];
            float4 br3 = *(const float4*)&sV[(kv0+3)*64 + tx*4];
#pragma unroll
            for (int i=0;i<8;i++){
                float4 a = *(const float4*)&sP[(ty*8+i)*PPAD + kv0];
                accO[i][0] += a.x*br0.x + a.y*br1.x + a.z*br2.x + a.w*br3.x;
                accO[i][1] += a.x*br0.y + a.y*br1.y + a.z*br2.y + a.w*br3.y;
                accO[i][2] += a.x*br0.z + a.y*br1.z + a.z*br2.z + a.w*br3.z;
                accO[i][3] += a.x*br0.w + a.y*br1.w + a.z*br2.w + a.w*br3.w;
            }
        }
    }

    // ---- normalize + write ----
#pragma unroll
    for (int i=0;i<8;i++){
        float inv = __fdividef(1.0f, lrow[i]);
        float4 o = {accO[i][0]*inv, accO[i][1]*inv, accO[i][2]*inv, accO[i][3]*inv};
        *(float4*)(g_oc + ((size_t)(b*TT + bm + ty*8 + i))*DD + h*HD + tx*4) = o;
    }
}

#define FLASH_SMEM ((64*128 + 64*64 + 64*64 + 128*PPAD)*4)

// ---------------- xproj: per (b,t), 16 dots of attn_out row with gate weights
__global__ void xproj_kernel(const float* __restrict__ Wf, const float* __restrict__ Wi,
                             const float* __restrict__ Wg, const float* __restrict__ Wo2,
                             const float* __restrict__ bf, const float* __restrict__ thf,
                             const float* __restrict__ bi, const float* __restrict__ thi,
                             const float* __restrict__ bg, const float* __restrict__ thg,
                             const float* __restrict__ bo2, const float* __restrict__ tho)
{
    __shared__ float sW[16][256];
    __shared__ float sBT[16];
    const int tid = threadIdx.x;
    {
        const float* Ws[4] = {Wf, Wi, Wg, Wo2};
        for (int i=tid; i<16*256; i+=256){
            int r = i>>8, k = i&255;
            sW[r][k] = Ws[r>>2][(r&3)*260 + k];
        }
        if (tid < 16){
            const float* bs[4] = {bf, bi, bg, bo2};
            const float* ts[4] = {thf, thi, thg, tho};
            sBT[tid] = bs[tid>>2][tid&3] + ts[tid>>2][tid&3];
        }
    }
    __syncthreads();
    const int m = blockIdx.x*8 + (tid>>5);    // row over (b,t)
    const int lane = tid & 31;
    const float* arow = g_att + (size_t)m*256;
    float av[8];
#pragma unroll
    for (int q=0;q<8;q++) av[q] = arow[lane + 32*q];
    float myval = 0.f;
#pragma unroll
    for (int r=0; r<16; r++){
        float acc = 0.f;
#pragma unroll
        for (int q=0;q<8;q++) acc += av[q]*sW[r][lane + 32*q];
#pragma unroll
        for (int off=16; off; off>>=1) acc += __shfl_xor_sync(0xffffffffu, acc, off);
        if (lane == r) myval = acc;
    }
    if (lane < 16){
        int b = m>>9, t = m&511;
        g_xp[((size_t)t*BB + b)*16 + lane] = myval + sBT[lane];
    }
}

// ---------------- sequential LSTM scan: 4 lanes per batch, no barriers -------
// Quantum layer closed form: <Z0>=C1C2C3, <Z1>=C0C1, <Z2>=C0C1C2, <Z3>=C0C1C2C3
__global__ void lstm_kernel(const float* __restrict__ Wf, const float* __restrict__ Wi,
                            const float* __restrict__ Wg, const float* __restrict__ Wo2)
{
    const int lane = threadIdx.x;
    const int gate = lane & 3;
    const int bat  = blockIdx.x*8 + (lane>>2);
    const float* Wsel = (gate==0)?Wf:(gate==1)?Wi:(gate==2)?Wg:Wo2;
    float wh[4][4];
#pragma unroll
    for (int j=0;j<4;j++)
#pragma unroll
        for (int m2=0;m2<4;m2++)
            wh[j][m2] = Wsel[j*260 + 256 + m2];
    const bool isg = (gate==2);
    float cx0=0,cx1=0,cx2=0,cx3=0;
    float hx0=0,hx1=0,hx2=0,hx3=0;
    const float4* xpp = (const float4*)g_xp;
    float4 cur = xpp[(size_t)bat*4 + gate];
    const int gb = lane & ~3;
    for (int t=0; t<TT; t++){
        float4 nxt = cur;
        if (t+1 < TT) nxt = xpp[((size_t)(t+1)*BB + bat)*4 + gate];
        float a0 = cur.x + hx0*wh[0][0]+hx1*wh[0][1]+hx2*wh[0][2]+hx3*wh[0][3];
        float a1 = cur.y + hx0*wh[1][0]+hx1*wh[1][1]+hx2*wh[1][2]+hx3*wh[1][3];
        float a2 = cur.z + hx0*wh[2][0]+hx1*wh[2][1]+hx2*wh[2][2]+hx3*wh[2][3];
        float a3 = cur.w + hx0*wh[3][0]+hx1*wh[3][1]+hx2*wh[3][2]+hx3*wh[3][3];
        float C0=__cosf(a0), C1=__cosf(a1), C2=__cosf(a2), C3=__cosf(a3);
        float t12 = C1*C2;
        float z0 = t12*C3, z1 = C0*C1, z2 = C0*t12, z3 = z2*C3;
        float v0,v1,v2,v3;
        if (isg){ v0=ftanh(z0); v1=ftanh(z1); v2=ftanh(z2); v3=ftanh(z3); }
        else    { v0=fsig(z0);  v1=fsig(z1);  v2=fsig(z2);  v3=fsig(z3); }
        float f0=__shfl_sync(0xffffffffu,v0,gb+0), i0=__shfl_sync(0xffffffffu,v0,gb+1),
              q0=__shfl_sync(0xffffffffu,v0,gb+2), o0=__shfl_sync(0xffffffffu,v0,gb+3);
        float f1=__shfl_sync(0xffffffffu,v1,gb+0), i1=__shfl_sync(0xffffffffu,v1,gb+1),
              q1=__shfl_sync(0xffffffffu,v1,gb+2), o1=__shfl_sync(0xffffffffu,v1,gb+3);
        float f2=__shfl_sync(0xffffffffu,v2,gb+0), i2=__shfl_sync(0xffffffffu,v2,gb+1),
              q2=__shfl_sync(0xffffffffu,v2,gb+2), o2=__shfl_sync(0xffffffffu,v2,gb+3);
        float f3=__shfl_sync(0xffffffffu,v3,gb+0), i3=__shfl_sync(0xffffffffu,v3,gb+1),
              q3=__shfl_sync(0xffffffffu,v3,gb+2), o3=__shfl_sync(0xffffffffu,v3,gb+3);
        cx0 = f0*cx0 + i0*q0;  hx0 = o0*ftanh(cx0);
        cx1 = f1*cx1 + i1*q1;  hx1 = o1*ftanh(cx1);
        cx2 = f2*cx2 + i2*q2;  hx2 = o2*ftanh(cx2);
        cx3 = f3*cx3 + i3*q3;  hx3 = o3*ftanh(cx3);
        float outv = (gate==0)?hx0:(gate==1)?hx1:(gate==2)?hx2:hx3;
        g_hs[((size_t)bat*TT + t)*4 + gate] = outv;
        cur = nxt;
    }
}

// ---------------- logits + log_softmax: one warp per (b,t) -------------------
__global__ void logits_kernel(const float* __restrict__ Wt,
                              const float* __restrict__ bt,
                              float* __restrict__ out)
{
    const int w = (blockIdx.x*blockDim.x + threadIdx.x) >> 5;   // 0..8191
    const int lane = threadIdx.x & 31;
    float4 h = *(const float4*)(g_hs + (size_t)w*4);
    int j0 = lane, j1 = lane + 32;
    float l0 = bt[j0] + h.x*Wt[j0*4+0] + h.y*Wt[j0*4+1] + h.z*Wt[j0*4+2] + h.w*Wt[j0*4+3];
    float l1 = bt[j1] + h.x*Wt[j1*4+0] + h.y*Wt[j1*4+1] + h.z*Wt[j1*4+2] + h.w*Wt[j1*4+3];
    float m = fmaxf(l0, l1);
#pragma unroll
    for (int off=16; off; off>>=1) m = fmaxf(m, __shfl_xor_sync(0xffffffffu, m, off));
    float s = __expf(l0-m) + __expf(l1-m);
#pragma unroll
    for (int off=16; off; off>>=1) s += __shfl_xor_sync(0xffffffffu, s, off);
    float ls = __logf(s) + m;
    out[(size_t)w*64 + j0] = l0 - ls;
    out[(size_t)w*64 + j1] = l1 - ls;
}

// ---------------- launch ------------------------------------------------------
extern "C" void kernel_launch(void* const* d_in, const int* in_sizes, int n_in,
                              void* d_out, int out_size)
{
    (void)in_sizes; (void)n_in; (void)out_size;
    const int*   sentence = (const int*)  d_in[0];
    const float* emb = (const float*)d_in[1];
    const float* Wq  = (const float*)d_in[2];  const float* bq  = (const float*)d_in[3];
    const float* Wk  = (const float*)d_in[4];  const float* bk  = (const float*)d_in[5];
    const float* Wv  = (const float*)d_in[6];  const float* bv  = (const float*)d_in[7];
    const float* Wo  = (const float*)d_in[8];  const float* bo  = (const float*)d_in[9];
    const float* Wf  = (const float*)d_in[10]; const float* bf  = (const float*)d_in[11];
    const float* thf = (const float*)d_in[12];
    const float* Wi  = (const float*)d_in[13]; const float* bi  = (const float*)d_in[14];
    const float* thi = (const float*)d_in[15];
    const float* Wg  = (const float*)d_in[16]; const float* bg  = (const float*)d_in[17];
    const float* thg = (const float*)d_in[18];
    const float* Wo2 = (const float*)d_in[19]; const float* bo2 = (const float*)d_in[20];
    const float* tho = (const float*)d_in[21];
    const float* Wt  = (const float*)d_in[22]; const float* bt  = (const float*)d_in[23];
    float* out = (float*)d_out;

    static bool attr_done = false;
    if (!attr_done){
        cudaFuncSetAttribute(flash_kernel,
                             cudaFuncAttributeMaxDynamicSharedMemorySize, FLASH_SMEM);
        attr_done = true;
    }

    // QKV: grid (M/128=64, N/128=2, 3)
    proj128_kernel<<<dim3(64, 2, 3), 256>>>(emb, sentence, Wq, bq, Wk, bk, Wv, bv, 0);
    // fused attention (scores + softmax + PV)
    flash_kernel<<<dim3(4, 64), 256, FLASH_SMEM>>>();
    // O-projection: sel=3, A=g_oc, W=Wo passed in Wq slot
    proj128_kernel<<<dim3(64, 2, 1), 256>>>(emb, sentence, Wo, bo, Wk, bk, Wv, bv, 3);
    xproj_kernel<<<1024, 256>>>(Wf,Wi,Wg,Wo2, bf,thf, bi,thi, bg,thg, bo2,tho);
    lstm_kernel<<<2, 32>>>(Wf, Wi, Wg, Wo2);
    logits_kernel<<<1024, 256>>>(Wt, bt, out);
}

// round 14
// speedup vs baseline: 1.3184x; 1.1707x over previous
#include <cuda_runtime.h>
#include <cstddef>

#define BB 16
#define TT 512
#define DD 256
#define HH 4
#define HD 64
#define MM (BB*TT)          // 8192

// ---------------- scratch (static device memory; no allocs) ----------------
__device__ float g_q[MM*DD];
__device__ float g_k[MM*DD];
__device__ float g_v[MM*DD];
__device__ float g_oc[MM*DD];
__device__ float g_att[MM*DD];
__device__ float g_xp[TT*BB*16];             // per-step gate pre-activations
__device__ float g_hs[BB*TT*4];              // lstm hidden outputs

__device__ __forceinline__ float fsig(float x){
    float e = __expf(-x);
    return __fdividef(1.0f, 1.0f + e);
}
__device__ __forceinline__ float ftanh(float x){
    float e = __expf(2.0f*x);
    return __fdividef(e - 1.0f, e + 1.0f);
}

__device__ __forceinline__ unsigned tf32u(float x){
    unsigned y; asm("cvt.rna.tf32.f32 %0, %1;" : "=r"(y) : "f"(x)); return y;
}
__device__ __forceinline__ float tf32f(float x){
    return __uint_as_float(tf32u(x));
}
__device__ __forceinline__ void mma_tf32(float&c0,float&c1,float&c2,float&c3,
    unsigned a0,unsigned a1,unsigned a2,unsigned a3,unsigned b0,unsigned b1){
    asm("mma.sync.aligned.m16n8k8.row.col.f32.tf32.tf32.f32 "
        "{%0,%1,%2,%3},{%4,%5,%6,%7},{%8,%9},{%0,%1,%2,%3};"
        : "+f"(c0),"+f"(c1),"+f"(c2),"+f"(c3)
        : "r"(a0),"r"(a1),"r"(a2),"r"(a3),"r"(b0),"r"(b1));
}

// ============================================================================
// 128x128-tile SGEMM with 8x8 per-thread microkernel, BK=8, double-buffered.
// ============================================================================
// sel 0/1/2: A = emb[idx[.]] (gather), C = g_q/g_k/g_v
// sel 3    : A = g_oc,                 C = g_att
__global__ __launch_bounds__(256, 2)
void proj128_kernel(const float* __restrict__ emb,
                    const int*   __restrict__ idx,
                    const float* __restrict__ Wq, const float* __restrict__ bq,
                    const float* __restrict__ Wk, const float* __restrict__ bk,
                    const float* __restrict__ Wv, const float* __restrict__ bv,
                    int sel_base)
{
    __shared__ float As[2][8][128];
    __shared__ float Bs[2][8][128];
    const int sel = sel_base + blockIdx.z;
    const float* W    = (sel==0)?Wq:(sel==1)?Wk:(sel==2)?Wv:Wq;   // sel3 passes Wo in Wq slot
    const float* bias = (sel==0)?bq:(sel==1)?bk:(sel==2)?bv:bq;
    float* C          = (sel==0)?g_q:(sel==1)?g_k:(sel==2)?g_v:g_att;
    const int tid = threadIdx.x;
    const int bm = blockIdx.x*128, bn = blockIdx.y*128;
    const int ty = tid>>4, tx = tid&15;
    const int lrow = tid>>1, lkc = (tid&1)<<2;   // loader: row 0..127, k-chunk 0/4

    const float* arow;
    if (sel < 3) arow = emb + (size_t)idx[bm+lrow]*DD + lkc;
    else         arow = g_oc + (size_t)(bm+lrow)*DD + lkc;
    const float* brow = W + (size_t)(bn+lrow)*DD + lkc;

    float acc[8][8] = {};
    float4 av = *(const float4*)(arow);
    float4 bv4 = *(const float4*)(brow);
    As[0][lkc+0][lrow]=av.x; As[0][lkc+1][lrow]=av.y; As[0][lkc+2][lrow]=av.z; As[0][lkc+3][lrow]=av.w;
    Bs[0][lkc+0][lrow]=bv4.x; Bs[0][lkc+1][lrow]=bv4.y; Bs[0][lkc+2][lrow]=bv4.z; Bs[0][lkc+3][lrow]=bv4.w;
    __syncthreads();

    const int NT = DD/8;   // 32
    for (int kt=0; kt<NT; kt++){
        int buf = kt & 1;
        if (kt+1 < NT){
            av  = *(const float4*)(arow + (kt+1)*8);
            bv4 = *(const float4*)(brow + (kt+1)*8);
        }
#pragma unroll
        for (int k=0;k<8;k++){
            float4 a0 = *(const float4*)&As[buf][k][ty*8];
            float4 a1 = *(const float4*)&As[buf][k][ty*8+4];
            float4 b0 = *(const float4*)&Bs[buf][k][tx*8];
            float4 b1 = *(const float4*)&Bs[buf][k][tx*8+4];
            float ar[8] = {a0.x,a0.y,a0.z,a0.w,a1.x,a1.y,a1.z,a1.w};
            float br[8] = {b0.x,b0.y,b0.z,b0.w,b1.x,b1.y,b1.z,b1.w};
#pragma unroll
            for (int i=0;i<8;i++)
#pragma unroll
                for (int j=0;j<8;j++)
                    acc[i][j] += ar[i]*br[j];
        }
        if (kt+1 < NT){
            int nb = (kt+1)&1;
            As[nb][lkc+0][lrow]=av.x; As[nb][lkc+1][lrow]=av.y; As[nb][lkc+2][lrow]=av.z; As[nb][lkc+3][lrow]=av.w;
            Bs[nb][lkc+0][lrow]=bv4.x; Bs[nb][lkc+1][lrow]=bv4.y; Bs[nb][lkc+2][lrow]=bv4.z; Bs[nb][lkc+3][lrow]=bv4.w;
            __syncthreads();
        }
    }
#pragma unroll
    for (int i=0;i<8;i++){
        float* crow = C + (size_t)(bm+ty*8+i)*DD + bn + tx*8;
        const float* bp = bias + bn + tx*8;
        float4 o0 = {acc[i][0]+bp[0], acc[i][1]+bp[1], acc[i][2]+bp[2], acc[i][3]+bp[3]};
        float4 o1 = {acc[i][4]+bp[4], acc[i][5]+bp[5], acc[i][6]+bp[6], acc[i][7]+bp[7]};
        *(float4*)crow = o0;
        *(float4*)(crow+4) = o1;
    }
}

// ============================================================================
// Fused flash attention on tensor cores (tf32 mma.sync m16n8k8).
// grid (4 m-chunks of 128 rows, 64 bh), 256 threads = 8 warps.
// Warp w owns M-tile rows 16w..16w+15. Online softmax over 8 KV tiles of 64.
// smem strides: sQ/sP 68, sK 68, sV 72 (all fragment loads conflict-free).
// ============================================================================
#define QS 68
#define KS 68
#define VS 72
#define PS 68
#define FLASH_SMEM ((128*QS + 64*KS + 64*VS + 128*PS)*4)

__global__ __launch_bounds__(256, 2)
void flash_kernel()
{
    extern __shared__ float sm[];
    float* sQ = sm;                 // [128][QS] tf32
    float* sK = sQ + 128*QS;        // [64][KS]  tf32 (n-major: sK[n][k])
    float* sV = sK + 64*KS;         // [64][VS]  tf32 (kv-major: sV[kv][d])
    float* sP = sV + 64*VS;         // [128][PS] tf32

    const int bh = blockIdx.y, b = bh>>2, h = bh&3;
    const int bm = blockIdx.x*128;
    const int tid = threadIdx.x;
    const int w = tid>>5, lane = tid&31;
    const int g = lane>>2, t = lane&3;      // groupID / threadID_in_group

    // ---- load Q chunk (tf32-converted, row-major) ----
    {
        int r = tid>>1, d0 = (tid&1)*32;
        const float* src = g_q + ((size_t)(b*TT + bm + r))*DD + h*HD + d0;
#pragma unroll
        for (int j=0;j<32;j+=4){
            float4 v = *(const float4*)(src + j);
            sQ[r*QS + d0 + j + 0] = tf32f(v.x);
            sQ[r*QS + d0 + j + 1] = tf32f(v.y);
            sQ[r*QS + d0 + j + 2] = tf32f(v.z);
            sQ[r*QS + d0 + j + 3] = tf32f(v.w);
        }
    }

    float o[8][4] = {};            // O fragments: [ntile][c0..c3]
    float m0=-1e30f, m1=-1e30f, l0=0.f, l1=0.f;

    const int arow0 = (16*w + g)*PS;      // sP/sQ row offsets for this thread
    const int arow1 = (16*w + g + 8)*PS;
    const int qrow0 = (16*w + g)*QS;
    const int qrow1 = (16*w + g + 8)*QS;

    for (int n0=0; n0<TT; n0+=64){
        __syncthreads();   // previous GEMM2 done reading sK/sV
        // ---- load K,V tile (tf32-converted) ----
        {
            int n = tid>>2, d0 = (tid&3)*16;
            const float* ksrc = g_k + ((size_t)(b*TT + n0 + n))*DD + h*HD + d0;
            const float* vsrc = g_v + ((size_t)(b*TT + n0 + n))*DD + h*HD + d0;
#pragma unroll
            for (int j=0;j<16;j+=4){
                float4 kv4 = *(const float4*)(ksrc + j);
                float4 vv4 = *(const float4*)(vsrc + j);
                sK[n*KS + d0 + j + 0] = tf32f(kv4.x);
                sK[n*KS + d0 + j + 1] = tf32f(kv4.y);
                sK[n*KS + d0 + j + 2] = tf32f(kv4.z);
                sK[n*KS + d0 + j + 3] = tf32f(kv4.w);
                sV[n*VS + d0 + j + 0] = tf32f(vv4.x);
                sV[n*VS + d0 + j + 1] = tf32f(vv4.y);
                sV[n*VS + d0 + j + 2] = tf32f(vv4.z);
                sV[n*VS + d0 + j + 3] = tf32f(vv4.w);
            }
        }
        __syncthreads();

        // ---- GEMM1: S(16x64) = Q-tile . K^T  (8 k-steps x 8 n-tiles) ----
        float s[8][4] = {};
#pragma unroll
        for (int kk=0; kk<8; kk++){
            const int ko = kk*8 + t;
            unsigned a0 = *(const unsigned*)&sQ[qrow0 + ko];
            unsigned a1 = *(const unsigned*)&sQ[qrow1 + ko];
            unsigned a2 = *(const unsigned*)&sQ[qrow0 + ko + 4];
            unsigned a3 = *(const unsigned*)&sQ[qrow1 + ko + 4];
#pragma unroll
            for (int j=0;j<8;j++){
                unsigned b0 = *(const unsigned*)&sK[(8*j+g)*KS + ko];
                unsigned b1 = *(const unsigned*)&sK[(8*j+g)*KS + ko + 4];
                mma_tf32(s[j][0],s[j][1],s[j][2],s[j][3], a0,a1,a2,a3, b0,b1);
            }
        }

        // ---- online softmax (rows g and g+8 of this M-tile) ----
        float lm0=-1e30f, lm1=-1e30f;
#pragma unroll
        for (int j=0;j<8;j++){
            s[j][0]*=0.125f; s[j][1]*=0.125f; s[j][2]*=0.125f; s[j][3]*=0.125f;
            lm0 = fmaxf(lm0, fmaxf(s[j][0], s[j][1]));
            lm1 = fmaxf(lm1, fmaxf(s[j][2], s[j][3]));
        }
        lm0 = fmaxf(lm0, __shfl_xor_sync(0xffffffffu, lm0, 1));
        lm0 = fmaxf(lm0, __shfl_xor_sync(0xffffffffu, lm0, 2));
        lm1 = fmaxf(lm1, __shfl_xor_sync(0xffffffffu, lm1, 1));
        lm1 = fmaxf(lm1, __shfl_xor_sync(0xffffffffu, lm1, 2));
        float nm0 = fmaxf(m0, lm0), nm1 = fmaxf(m1, lm1);
        float c0 = __expf(m0 - nm0), c1 = __expf(m1 - nm1);
        m0 = nm0; m1 = nm1;
        float ls0 = 0.f, ls1 = 0.f;
#pragma unroll
        for (int j=0;j<8;j++){
            float p00 = __expf(s[j][0]-nm0), p01 = __expf(s[j][1]-nm0);
            float p10 = __expf(s[j][2]-nm1), p11 = __expf(s[j][3]-nm1);
            ls0 += p00 + p01;  ls1 += p10 + p11;
            int cb = 8*j + 2*t;
            sP[arow0 + cb]     = tf32f(p00);
            sP[arow0 + cb + 1] = tf32f(p01);
            sP[arow1 + cb]     = tf32f(p10);
            sP[arow1 + cb + 1] = tf32f(p11);
        }
        ls0 += __shfl_xor_sync(0xffffffffu, ls0, 1);
        ls0 += __shfl_xor_sync(0xffffffffu, ls0, 2);
        ls1 += __shfl_xor_sync(0xffffffffu, ls1, 1);
        ls1 += __shfl_xor_sync(0xffffffffu, ls1, 2);
        l0 = l0*c0 + ls0;  l1 = l1*c1 + ls1;
#pragma unroll
        for (int j=0;j<8;j++){
            o[j][0]*=c0; o[j][1]*=c0; o[j][2]*=c1; o[j][3]*=c1;
        }
        __syncwarp();      // sP rows of this M-tile written only by this warp

        // ---- GEMM2: O(16x64) += P(16x64) . V(64x64) ----
#pragma unroll
        for (int kk=0; kk<8; kk++){
            const int ko = kk*8 + t;
            unsigned a0 = *(const unsigned*)&sP[arow0 + ko];
            unsigned a1 = *(const unsigned*)&sP[arow1 + ko];
            unsigned a2 = *(const unsigned*)&sP[arow0 + ko + 4];
            unsigned a3 = *(const unsigned*)&sP[arow1 + ko + 4];
#pragma unroll
            for (int j=0;j<8;j++){
                unsigned b0 = *(const unsigned*)&sV[ko*VS + 8*j + g];
                unsigned b1 = *(const unsigned*)&sV[(ko+4)*VS + 8*j + g];
                mma_tf32(o[j][0],o[j][1],o[j][2],o[j][3], a0,a1,a2,a3, b0,b1);
            }
        }
        __syncwarp();      // done reading this warp's sP rows before next overwrite
    }

    // ---- normalize + write ----
    float inv0 = __fdividef(1.0f, l0), inv1 = __fdividef(1.0f, l1);
    float* out0 = g_oc + ((size_t)(b*TT + bm + 16*w + g))*DD + h*HD;
    float* out1 = g_oc + ((size_t)(b*TT + bm + 16*w + g + 8))*DD + h*HD;
#pragma unroll
    for (int j=0;j<8;j++){
        int cb = 8*j + 2*t;
        float2 v0 = {o[j][0]*inv0, o[j][1]*inv0};
        float2 v1 = {o[j][2]*inv1, o[j][3]*inv1};
        *(float2*)(out0 + cb) = v0;
        *(float2*)(out1 + cb) = v1;
    }
}

// ---------------- xproj: per (b,t), 16 dots of attn_out row with gate weights
__global__ void xproj_kernel(const float* __restrict__ Wf, const float* __restrict__ Wi,
                             const float* __restrict__ Wg, const float* __restrict__ Wo2,
                             const float* __restrict__ bf, const float* __restrict__ thf,
                             const float* __restrict__ bi, const float* __restrict__ thi,
                             const float* __restrict__ bg, const float* __restrict__ thg,
                             const float* __restrict__ bo2, const float* __restrict__ tho)
{
    __shared__ float sW[16][256];
    __shared__ float sBT[16];
    const int tid = threadIdx.x;
    {
        const float* Ws[4] = {Wf, Wi, Wg, Wo2};
        for (int i=tid; i<16*256; i+=256){
            int r = i>>8, k = i&255;
            sW[r][k] = Ws[r>>2][(r&3)*260 + k];
        }
        if (tid < 16){
            const float* bs[4] = {bf, bi, bg, bo2};
            const float* ts[4] = {thf, thi, thg, tho};
            sBT[tid] = bs[tid>>2][tid&3] + ts[tid>>2][tid&3];
        }
    }
    __syncthreads();
    const int m = blockIdx.x*8 + (tid>>5);    // row over (b,t)
    const int lane = tid & 31;
    const float* arow = g_att + (size_t)m*256;
    float av[8];
#pragma unroll
    for (int q=0;q<8;q++) av[q] = arow[lane + 32*q];
    float myval = 0.f;
#pragma unroll
    for (int r=0; r<16; r++){
        float acc = 0.f;
#pragma unroll
        for (int q=0;q<8;q++) acc += av[q]*sW[r][lane + 32*q];
#pragma unroll
        for (int off=16; off; off>>=1) acc += __shfl_xor_sync(0xffffffffu, acc, off);
        if (lane == r) myval = acc;
    }
    if (lane < 16){
        int b = m>>9, t = m&511;
        g_xp[((size_t)t*BB + b)*16 + lane] = myval + sBT[lane];
    }
}

// ---------------- sequential LSTM scan: 4 lanes per batch, no barriers -------
// Quantum layer closed form: <Z0>=C1C2C3, <Z1>=C0C1, <Z2>=C0C1C2, <Z3>=C0C1C2C3
__global__ void lstm_kernel(const float* __restrict__ Wf, const float* __restrict__ Wi,
                            const float* __restrict__ Wg, const float* __restrict__ Wo2)
{
    const int lane = threadIdx.x;
    const int gate = lane & 3;
    const int bat  = blockIdx.x*8 + (lane>>2);
    const float* Wsel = (gate==0)?Wf:(gate==1)?Wi:(gate==2)?Wg:Wo2;
    float wh[4][4];
#pragma unroll
    for (int j=0;j<4;j++)
#pragma unroll
        for (int m2=0;m2<4;m2++)
            wh[j][m2] = Wsel[j*260 + 256 + m2];
    const bool isg = (gate==2);
    float cx0=0,cx1=0,cx2=0,cx3=0;
    float hx0=0,hx1=0,hx2=0,hx3=0;
    const float4* xpp = (const float4*)g_xp;
    float4 cur = xpp[(size_t)bat*4 + gate];
    const int gb = lane & ~3;
    for (int t=0; t<TT; t++){
        float4 nxt = cur;
        if (t+1 < TT) nxt = xpp[((size_t)(t+1)*BB + bat)*4 + gate];
        float a0 = cur.x + hx0*wh[0][0]+hx1*wh[0][1]+hx2*wh[0][2]+hx3*wh[0][3];
        float a1 = cur.y + hx0*wh[1][0]+hx1*wh[1][1]+hx2*wh[1][2]+hx3*wh[1][3];
        float a2 = cur.z + hx0*wh[2][0]+hx1*wh[2][1]+hx2*wh[2][2]+hx3*wh[2][3];
        float a3 = cur.w + hx0*wh[3][0]+hx1*wh[3][1]+hx2*wh[3][2]+hx3*wh[3][3];
        float C0=__cosf(a0), C1=__cosf(a1), C2=__cosf(a2), C3=__cosf(a3);
        float t12 = C1*C2;
        float z0 = t12*C3, z1 = C0*C1, z2 = C0*t12, z3 = z2*C3;
        float v0,v1,v2,v3;
        if (isg){ v0=ftanh(z0); v1=ftanh(z1); v2=ftanh(z2); v3=ftanh(z3); }
        else    { v0=fsig(z0);  v1=fsig(z1);  v2=fsig(z2);  v3=fsig(z3); }
        float f0=__shfl_sync(0xffffffffu,v0,gb+0), i0=__shfl_sync(0xffffffffu,v0,gb+1),
              q0=__shfl_sync(0xffffffffu,v0,gb+2), o0=__shfl_sync(0xffffffffu,v0,gb+3);
        float f1=__shfl_sync(0xffffffffu,v1,gb+0), i1=__shfl_sync(0xffffffffu,v1,gb+1),
              q1=__shfl_sync(0xffffffffu,v1,gb+2), o1=__shfl_sync(0xffffffffu,v1,gb+3);
        float f2=__shfl_sync(0xffffffffu,v2,gb+0), i2=__shfl_sync(0xffffffffu,v2,gb+1),
              q2=__shfl_sync(0xffffffffu,v2,gb+2), o2=__shfl_sync(0xffffffffu,v2,gb+3);
        float f3=__shfl_sync(0xffffffffu,v3,gb+0), i3=__shfl_sync(0xffffffffu,v3,gb+1),
              q3=__shfl_sync(0xffffffffu,v3,gb+2), o3=__shfl_sync(0xffffffffu,v3,gb+3);
        cx0 = f0*cx0 + i0*q0;  hx0 = o0*ftanh(cx0);
        cx1 = f1*cx1 + i1*q1;  hx1 = o1*ftanh(cx1);
        cx2 = f2*cx2 + i2*q2;  hx2 = o2*ftanh(cx2);
        cx3 = f3*cx3 + i3*q3;  hx3 = o3*ftanh(cx3);
        float outv = (gate==0)?hx0:(gate==1)?hx1:(gate==2)?hx2:hx3;
        g_hs[((size_t)bat*TT + t)*4 + gate] = outv;
        cur = nxt;
    }
}

// ---------------- logits + log_softmax: one warp per (b,t) -------------------
__global__ void logits_kernel(const float* __restrict__ Wt,
                              const float* __restrict__ bt,
                              float* __restrict__ out)
{
    const int w = (blockIdx.x*blockDim.x + threadIdx.x) >> 5;   // 0..8191
    const int lane = threadIdx.x & 31;
    float4 h = *(const float4*)(g_hs + (size_t)w*4);
    int j0 = lane, j1 = lane + 32;
    float l0 = bt[j0] + h.x*Wt[j0*4+0] + h.y*Wt[j0*4+1] + h.z*Wt[j0*4+2] + h.w*Wt[j0*4+3];
    float l1 = bt[j1] + h.x*Wt[j1*4+0] + h.y*Wt[j1*4+1] + h.z*Wt[j1*4+2] + h.w*Wt[j1*4+3];
    float m = fmaxf(l0, l1);
#pragma unroll
    for (int off=16; off; off>>=1) m = fmaxf(m, __shfl_xor_sync(0xffffffffu, m, off));
    float s = __expf(l0-m) + __expf(l1-m);
#pragma unroll
    for (int off=16; off; off>>=1) s += __shfl_xor_sync(0xffffffffu, s, off);
    float ls = __logf(s) + m;
    out[(size_t)w*64 + j0] = l0 - ls;
    out[(size_t)w*64 + j1] = l1 - ls;
}

// ---------------- launch ------------------------------------------------------
extern "C" void kernel_launch(void* const* d_in, const int* in_sizes, int n_in,
                              void* d_out, int out_size)
{
    (void)in_sizes; (void)n_in; (void)out_size;
    const int*   sentence = (const int*)  d_in[0];
    const float* emb = (const float*)d_in[1];
    const float* Wq  = (const float*)d_in[2];  const float* bq  = (const float*)d_in[3];
    const float* Wk  = (const float*)d_in[4];  const float* bk  = (const float*)d_in[5];
    const float* Wv  = (const float*)d_in[6];  const float* bv  = (const float*)d_in[7];
    const float* Wo  = (const float*)d_in[8];  const float* bo  = (const float*)d_in[9];
    const float* Wf  = (const float*)d_in[10]; const float* bf  = (const float*)d_in[11];
    const float* thf = (const float*)d_in[12];
    const float* Wi  = (const float*)d_in[13]; const float* bi  = (const float*)d_in[14];
    const float* thi = (const float*)d_in[15];
    const float* Wg  = (const float*)d_in[16]; const float* bg  = (const float*)d_in[17];
    const float* thg = (const float*)d_in[18];
    const float* Wo2 = (const float*)d_in[19]; const float* bo2 = (const float*)d_in[20];
    const float* tho = (const float*)d_in[21];
    const float* Wt  = (const float*)d_in[22]; const float* bt  = (const float*)d_in[23];
    float* out = (float*)d_out;

    static bool attr_done = false;
    if (!attr_done){
        cudaFuncSetAttribute(flash_kernel,
                             cudaFuncAttributeMaxDynamicSharedMemorySize, FLASH_SMEM);
        attr_done = true;
    }

    // QKV: grid (M/128=64, N/128=2, 3)
    proj128_kernel<<<dim3(64, 2, 3), 256>>>(emb, sentence, Wq, bq, Wk, bk, Wv, bv, 0);
    // fused attention (scores + softmax + PV) on tensor cores
    flash_kernel<<<dim3(4, 64), 256, FLASH_SMEM>>>();
    // O-projection: sel=3, A=g_oc, W=Wo passed in Wq slot
    proj128_kernel<<<dim3(64, 2, 1), 256>>>(emb, sentence, Wo, bo, Wk, bk, Wv, bv, 3);
    xproj_kernel<<<1024, 256>>>(Wf,Wi,Wg,Wo2, bf,thf, bi,thi, bg,thg, bo2,tho);
    lstm_kernel<<<2, 32>>>(Wf, Wi, Wg, Wo2);
    logits_kernel<<<1024, 256>>>(Wt, bt, out);
}

// round 15
// speedup vs baseline: 1.5606x; 1.1836x over previous
#include <cuda_runtime.h>
#include <cstddef>

#define BB 16
#define TT 512
#define DD 256
#define HH 4
#define HD 64
#define MM (BB*TT)          // 8192

// ---------------- scratch (static device memory; no allocs) ----------------
__device__ float g_q[MM*DD];
__device__ float g_k[MM*DD];
__device__ float g_v[MM*DD];
__device__ float g_oc[MM*DD];
__device__ float g_att[MM*DD];
__device__ float g_xp[TT*BB*16];             // per-step gate pre-activations
__device__ float g_hs[BB*TT*4];              // lstm hidden outputs

__device__ __forceinline__ float fsig(float x){
    float e = __expf(-x);
    return __fdividef(1.0f, 1.0f + e);
}
__device__ __forceinline__ float ftanh(float x){
    float e = __expf(2.0f*x);
    return __fdividef(e - 1.0f, e + 1.0f);
}

__device__ __forceinline__ unsigned tf32u(float x){
    unsigned y; asm("cvt.rna.tf32.f32 %0, %1;" : "=r"(y) : "f"(x)); return y;
}
__device__ __forceinline__ float tf32f(float x){
    return __uint_as_float(tf32u(x));
}
__device__ __forceinline__ void mma_tf32(float&c0,float&c1,float&c2,float&c3,
    unsigned a0,unsigned a1,unsigned a2,unsigned a3,unsigned b0,unsigned b1){
    asm("mma.sync.aligned.m16n8k8.row.col.f32.tf32.tf32.f32 "
        "{%0,%1,%2,%3},{%4,%5,%6,%7},{%8,%9},{%0,%1,%2,%3};"
        : "+f"(c0),"+f"(c1),"+f"(c2),"+f"(c3)
        : "r"(a0),"r"(a1),"r"(a2),"r"(a3),"r"(b0),"r"(b1));
}

// ============================================================================
// Projection GEMM on tensor cores (tf32 mma.sync m16n8k8).
// C[M=8192, N=256] = A[M,256] @ W[N,256]^T + bias.
// Grid (M/128, N/64, nsel), 256 threads = 8 warps; warp w owns rows 16w..16w+15
// of the block's 128x64 C-tile. K consumed in 8 chunks of 32 via smem.
// sel 0/1/2: A = emb[idx[.]] (gather), C = g_q/g_k/g_v
// sel 3    : A = g_oc,                 C = g_att
// ============================================================================
#define AS 36
#define WS 36

__global__ __launch_bounds__(256, 2)
void proj_mma_kernel(const float* __restrict__ emb,
                     const int*   __restrict__ idx,
                     const float* __restrict__ Wq, const float* __restrict__ bq,
                     const float* __restrict__ Wk, const float* __restrict__ bk,
                     const float* __restrict__ Wv, const float* __restrict__ bv,
                     int sel_base)
{
    __shared__ float sA[128*AS];
    __shared__ float sW[64*WS];
    const int sel = sel_base + blockIdx.z;
    const float* Wm   = (sel==0)?Wq:(sel==1)?Wk:(sel==2)?Wv:Wq;   // sel3: Wo in Wq slot
    const float* bias = (sel==0)?bq:(sel==1)?bk:(sel==2)?bv:bq;
    float* C          = (sel==0)?g_q:(sel==1)?g_k:(sel==2)?g_v:g_att;
    const int tid = threadIdx.x;
    const int bm = blockIdx.x*128, bn = blockIdx.y*64;
    const int w = tid>>5, lane = tid&31;
    const int g = lane>>2, t = lane&3;

    // loader mappings
    const int ar = tid>>1, ac0 = (tid&1)*16;        // A: row, 16 cols
    const int wr = tid>>2, wc0 = (tid&3)*8;         // W: row, 8 cols
    const float* arow;
    if (sel < 3) arow = emb + (size_t)idx[bm+ar]*DD + ac0;
    else         arow = g_oc + (size_t)(bm+ar)*DD + ac0;
    const float* brow = Wm + (size_t)(bn+wr)*DD + wc0;

    float s[8][4] = {};
    const int qrow0 = (16*w + g)*AS;
    const int qrow1 = (16*w + g + 8)*AS;

#pragma unroll 1
    for (int kc=0; kc<8; kc++){
        __syncthreads();
        // load A chunk [128][32] (tf32-converted)
#pragma unroll
        for (int j=0;j<16;j+=4){
            float4 v = *(const float4*)(arow + kc*32 + j);
            sA[ar*AS + ac0 + j + 0] = tf32f(v.x);
            sA[ar*AS + ac0 + j + 1] = tf32f(v.y);
            sA[ar*AS + ac0 + j + 2] = tf32f(v.z);
            sA[ar*AS + ac0 + j + 3] = tf32f(v.w);
        }
        // load W chunk [64][32]
#pragma unroll
        for (int j=0;j<8;j+=4){
            float4 v = *(const float4*)(brow + kc*32 + j);
            sW[wr*WS + wc0 + j + 0] = tf32f(v.x);
            sW[wr*WS + wc0 + j + 1] = tf32f(v.y);
            sW[wr*WS + wc0 + j + 2] = tf32f(v.z);
            sW[wr*WS + wc0 + j + 3] = tf32f(v.w);
        }
        __syncthreads();

#pragma unroll
        for (int kk=0; kk<4; kk++){
            const int ko = kk*8 + t;
            unsigned a0 = *(const unsigned*)&sA[qrow0 + ko];
            unsigned a1 = *(const unsigned*)&sA[qrow1 + ko];
            unsigned a2 = *(const unsigned*)&sA[qrow0 + ko + 4];
            unsigned a3 = *(const unsigned*)&sA[qrow1 + ko + 4];
#pragma unroll
            for (int j=0;j<8;j++){
                unsigned b0 = *(const unsigned*)&sW[(8*j+g)*WS + ko];
                unsigned b1 = *(const unsigned*)&sW[(8*j+g)*WS + ko + 4];
                mma_tf32(s[j][0],s[j][1],s[j][2],s[j][3], a0,a1,a2,a3, b0,b1);
            }
        }
    }

    // epilogue: bias + store (rows 16w+g, 16w+g+8; cols bn+8j+2t, +1)
    float* out0 = C + (size_t)(bm + 16*w + g)*DD + bn;
    float* out1 = C + (size_t)(bm + 16*w + g + 8)*DD + bn;
#pragma unroll
    for (int j=0;j<8;j++){
        int cb = 8*j + 2*t;
        float b0 = bias[bn + cb], b1 = bias[bn + cb + 1];
        float2 v0 = {s[j][0]+b0, s[j][1]+b1};
        float2 v1 = {s[j][2]+b0, s[j][3]+b1};
        *(float2*)(out0 + cb) = v0;
        *(float2*)(out1 + cb) = v1;
    }
}

// ============================================================================
// Fused flash attention on tensor cores (tf32 mma.sync m16n8k8).
// grid (4 m-chunks of 128 rows, 64 bh), 256 threads = 8 warps.
// ============================================================================
#define QS 68
#define KS 68
#define VS 72
#define PS 68
#define FLASH_SMEM ((128*QS + 64*KS + 64*VS + 128*PS)*4)

__global__ __launch_bounds__(256, 2)
void flash_kernel()
{
    extern __shared__ float sm[];
    float* sQ = sm;                 // [128][QS] tf32
    float* sK = sQ + 128*QS;        // [64][KS]  tf32 (n-major: sK[n][k])
    float* sV = sK + 64*KS;         // [64][VS]  tf32 (kv-major: sV[kv][d])
    float* sP = sV + 64*VS;         // [128][PS] tf32

    const int bh = blockIdx.y, b = bh>>2, h = bh&3;
    const int bm = blockIdx.x*128;
    const int tid = threadIdx.x;
    const int w = tid>>5, lane = tid&31;
    const int g = lane>>2, t = lane&3;      // groupID / threadID_in_group

    // ---- load Q chunk (tf32-converted, row-major) ----
    {
        int r = tid>>1, d0 = (tid&1)*32;
        const float* src = g_q + ((size_t)(b*TT + bm + r))*DD + h*HD + d0;
#pragma unroll
        for (int j=0;j<32;j+=4){
            float4 v = *(const float4*)(src + j);
            sQ[r*QS + d0 + j + 0] = tf32f(v.x);
            sQ[r*QS + d0 + j + 1] = tf32f(v.y);
            sQ[r*QS + d0 + j + 2] = tf32f(v.z);
            sQ[r*QS + d0 + j + 3] = tf32f(v.w);
        }
    }

    float o[8][4] = {};            // O fragments: [ntile][c0..c3]
    float m0=-1e30f, m1=-1e30f, l0=0.f, l1=0.f;

    const int arow0 = (16*w + g)*PS;
    const int arow1 = (16*w + g + 8)*PS;
    const int qrow0 = (16*w + g)*QS;
    const int qrow1 = (16*w + g + 8)*QS;

    for (int n0=0; n0<TT; n0+=64){
        __syncthreads();   // previous GEMM2 done reading sK/sV
        // ---- load K,V tile (tf32-converted) ----
        {
            int n = tid>>2, d0 = (tid&3)*16;
            const float* ksrc = g_k + ((size_t)(b*TT + n0 + n))*DD + h*HD + d0;
            const float* vsrc = g_v + ((size_t)(b*TT + n0 + n))*DD + h*HD + d0;
#pragma unroll
            for (int j=0;j<16;j+=4){
                float4 kv4 = *(const float4*)(ksrc + j);
                float4 vv4 = *(const float4*)(vsrc + j);
                sK[n*KS + d0 + j + 0] = tf32f(kv4.x);
                sK[n*KS + d0 + j + 1] = tf32f(kv4.y);
                sK[n*KS + d0 + j + 2] = tf32f(kv4.z);
                sK[n*KS + d0 + j + 3] = tf32f(kv4.w);
                sV[n*VS + d0 + j + 0] = tf32f(vv4.x);
                sV[n*VS + d0 + j + 1] = tf32f(vv4.y);
                sV[n*VS + d0 + j + 2] = tf32f(vv4.z);
                sV[n*VS + d0 + j + 3] = tf32f(vv4.w);
            }
        }
        __syncthreads();

        // ---- GEMM1: S(16x64) = Q-tile . K^T ----
        float s[8][4] = {};
#pragma unroll
        for (int kk=0; kk<8; kk++){
            const int ko = kk*8 + t;
            unsigned a0 = *(const unsigned*)&sQ[qrow0 + ko];
            unsigned a1 = *(const unsigned*)&sQ[qrow1 + ko];
            unsigned a2 = *(const unsigned*)&sQ[qrow0 + ko + 4];
            unsigned a3 = *(const unsigned*)&sQ[qrow1 + ko + 4];
#pragma unroll
            for (int j=0;j<8;j++){
                unsigned b0 = *(const unsigned*)&sK[(8*j+g)*KS + ko];
                unsigned b1 = *(const unsigned*)&sK[(8*j+g)*KS + ko + 4];
                mma_tf32(s[j][0],s[j][1],s[j][2],s[j][3], a0,a1,a2,a3, b0,b1);
            }
        }

        // ---- online softmax ----
        float lm0=-1e30f, lm1=-1e30f;
#pragma unroll
        for (int j=0;j<8;j++){
            s[j][0]*=0.125f; s[j][1]*=0.125f; s[j][2]*=0.125f; s[j][3]*=0.125f;
            lm0 = fmaxf(lm0, fmaxf(s[j][0], s[j][1]));
            lm1 = fmaxf(lm1, fmaxf(s[j][2], s[j][3]));
        }
        lm0 = fmaxf(lm0, __shfl_xor_sync(0xffffffffu, lm0, 1));
        lm0 = fmaxf(lm0, __shfl_xor_sync(0xffffffffu, lm0, 2));
        lm1 = fmaxf(lm1, __shfl_xor_sync(0xffffffffu, lm1, 1));
        lm1 = fmaxf(lm1, __shfl_xor_sync(0xffffffffu, lm1, 2));
        float nm0 = fmaxf(m0, lm0), nm1 = fmaxf(m1, lm1);
        float c0 = __expf(m0 - nm0), c1 = __expf(m1 - nm1);
        m0 = nm0; m1 = nm1;
        float ls0 = 0.f, ls1 = 0.f;
#pragma unroll
        for (int j=0;j<8;j++){
            float p00 = __expf(s[j][0]-nm0), p01 = __expf(s[j][1]-nm0);
            float p10 = __expf(s[j][2]-nm1), p11 = __expf(s[j][3]-nm1);
            ls0 += p00 + p01;  ls1 += p10 + p11;
            int cb = 8*j + 2*t;
            sP[arow0 + cb]     = tf32f(p00);
            sP[arow0 + cb + 1] = tf32f(p01);
            sP[arow1 + cb]     = tf32f(p10);
            sP[arow1 + cb + 1] = tf32f(p11);
        }
        ls0 += __shfl_xor_sync(0xffffffffu, ls0, 1);
        ls0 += __shfl_xor_sync(0xffffffffu, ls0, 2);
        ls1 += __shfl_xor_sync(0xffffffffu, ls1, 1);
        ls1 += __shfl_xor_sync(0xffffffffu, ls1, 2);
        l0 = l0*c0 + ls0;  l1 = l1*c1 + ls1;
#pragma unroll
        for (int j=0;j<8;j++){
            o[j][0]*=c0; o[j][1]*=c0; o[j][2]*=c1; o[j][3]*=c1;
        }
        __syncwarp();      // sP rows of this M-tile written only by this warp

        // ---- GEMM2: O(16x64) += P(16x64) . V(64x64) ----
#pragma unroll
        for (int kk=0; kk<8; kk++){
            const int ko = kk*8 + t;
            unsigned a0 = *(const unsigned*)&sP[arow0 + ko];
            unsigned a1 = *(const unsigned*)&sP[arow1 + ko];
            unsigned a2 = *(const unsigned*)&sP[arow0 + ko + 4];
            unsigned a3 = *(const unsigned*)&sP[arow1 + ko + 4];
#pragma unroll
            for (int j=0;j<8;j++){
                unsigned b0 = *(const unsigned*)&sV[ko*VS + 8*j + g];
                unsigned b1 = *(const unsigned*)&sV[(ko+4)*VS + 8*j + g];
                mma_tf32(o[j][0],o[j][1],o[j][2],o[j][3], a0,a1,a2,a3, b0,b1);
            }
        }
        __syncwarp();
    }

    // ---- normalize + write ----
    float inv0 = __fdividef(1.0f, l0), inv1 = __fdividef(1.0f, l1);
    float* out0 = g_oc + ((size_t)(b*TT + bm + 16*w + g))*DD + h*HD;
    float* out1 = g_oc + ((size_t)(b*TT + bm + 16*w + g + 8))*DD + h*HD;
#pragma unroll
    for (int j=0;j<8;j++){
        int cb = 8*j + 2*t;
        float2 v0 = {o[j][0]*inv0, o[j][1]*inv0};
        float2 v1 = {o[j][2]*inv1, o[j][3]*inv1};
        *(float2*)(out0 + cb) = v0;
        *(float2*)(out1 + cb) = v1;
    }
}

// ---------------- xproj: per (b,t), 16 dots of attn_out row with gate weights
__global__ void xproj_kernel(const float* __restrict__ Wf, const float* __restrict__ Wi,
                             const float* __restrict__ Wg, const float* __restrict__ Wo2,
                             const float* __restrict__ bf, const float* __restrict__ thf,
                             const float* __restrict__ bi, const float* __restrict__ thi,
                             const float* __restrict__ bg, const float* __restrict__ thg,
                             const float* __restrict__ bo2, const float* __restrict__ tho)
{
    __shared__ float sW[16][256];
    __shared__ float sBT[16];
    const int tid = threadIdx.x;
    {
        const float* Ws[4] = {Wf, Wi, Wg, Wo2};
        for (int i=tid; i<16*256; i+=256){
            int r = i>>8, k = i&255;
            sW[r][k] = Ws[r>>2][(r&3)*260 + k];
        }
        if (tid < 16){
            const float* bs[4] = {bf, bi, bg, bo2};
            const float* ts[4] = {thf, thi, thg, tho};
            sBT[tid] = bs[tid>>2][tid&3] + ts[tid>>2][tid&3];
        }
    }
    __syncthreads();
    const int m = blockIdx.x*8 + (tid>>5);    // row over (b,t)
    const int lane = tid & 31;
    const float* arow = g_att + (size_t)m*256;
    float av[8];
#pragma unroll
    for (int q=0;q<8;q++) av[q] = arow[lane + 32*q];
    float myval = 0.f;
#pragma unroll
    for (int r=0; r<16; r++){
        float acc = 0.f;
#pragma unroll
        for (int q=0;q<8;q++) acc += av[q]*sW[r][lane + 32*q];
#pragma unroll
        for (int off=16; off; off>>=1) acc += __shfl_xor_sync(0xffffffffu, acc, off);
        if (lane == r) myval = acc;
    }
    if (lane < 16){
        int b = m>>9, t = m&511;
        g_xp[((size_t)t*BB + b)*16 + lane] = myval + sBT[lane];
    }
}

// ---------------- sequential LSTM scan: 4 lanes per batch, no barriers -------
// Quantum layer closed form: <Z0>=C1C2C3, <Z1>=C0C1, <Z2>=C0C1C2, <Z3>=C0C1C2C3
__global__ void lstm_kernel(const float* __restrict__ Wf, const float* __restrict__ Wi,
                            const float* __restrict__ Wg, const float* __restrict__ Wo2)
{
    const int lane = threadIdx.x;
    const int gate = lane & 3;
    const int bat  = blockIdx.x*8 + (lane>>2);
    const float* Wsel = (gate==0)?Wf:(gate==1)?Wi:(gate==2)?Wg:Wo2;
    float wh[4][4];
#pragma unroll
    for (int j=0;j<4;j++)
#pragma unroll
        for (int m2=0;m2<4;m2++)
            wh[j][m2] = Wsel[j*260 + 256 + m2];
    const bool isg = (gate==2);
    float cx0=0,cx1=0,cx2=0,cx3=0;
    float hx0=0,hx1=0,hx2=0,hx3=0;
    const float4* xpp = (const float4*)g_xp;
    float4 cur = xpp[(size_t)bat*4 + gate];
    const int gb = lane & ~3;
    for (int t=0; t<TT; t++){
        float4 nxt = cur;
        if (t+1 < TT) nxt = xpp[((size_t)(t+1)*BB + bat)*4 + gate];
        float a0 = cur.x + hx0*wh[0][0]+hx1*wh[0][1]+hx2*wh[0][2]+hx3*wh[0][3];
        float a1 = cur.y + hx0*wh[1][0]+hx1*wh[1][1]+hx2*wh[1][2]+hx3*wh[1][3];
        float a2 = cur.z + hx0*wh[2][0]+hx1*wh[2][1]+hx2*wh[2][2]+hx3*wh[2][3];
        float a3 = cur.w + hx0*wh[3][0]+hx1*wh[3][1]+hx2*wh[3][2]+hx3*wh[3][3];
        float C0=__cosf(a0), C1=__cosf(a1), C2=__cosf(a2), C3=__cosf(a3);
        float t12 = C1*C2;
        float z0 = t12*C3, z1 = C0*C1, z2 = C0*t12, z3 = z2*C3;
        float v0,v1,v2,v3;
        if (isg){ v0=ftanh(z0); v1=ftanh(z1); v2=ftanh(z2); v3=ftanh(z3); }
        else    { v0=fsig(z0);  v1=fsig(z1);  v2=fsig(z2);  v3=fsig(z3); }
        float f0=__shfl_sync(0xffffffffu,v0,gb+0), i0=__shfl_sync(0xffffffffu,v0,gb+1),
              q0=__shfl_sync(0xffffffffu,v0,gb+2), o0=__shfl_sync(0xffffffffu,v0,gb+3);
        float f1=__shfl_sync(0xffffffffu,v1,gb+0), i1=__shfl_sync(0xffffffffu,v1,gb+1),
              q1=__shfl_sync(0xffffffffu,v1,gb+2), o1=__shfl_sync(0xffffffffu,v1,gb+3);
        float f2=__shfl_sync(0xffffffffu,v2,gb+0), i2=__shfl_sync(0xffffffffu,v2,gb+1),
              q2=__shfl_sync(0xffffffffu,v2,gb+2), o2=__shfl_sync(0xffffffffu,v2,gb+3);
        float f3=__shfl_sync(0xffffffffu,v3,gb+0), i3=__shfl_sync(0xffffffffu,v3,gb+1),
              q3=__shfl_sync(0xffffffffu,v3,gb+2), o3=__shfl_sync(0xffffffffu,v3,gb+3);
        cx0 = f0*cx0 + i0*q0;  hx0 = o0*ftanh(cx0);
        cx1 = f1*cx1 + i1*q1;  hx1 = o1*ftanh(cx1);
        cx2 = f2*cx2 + i2*q2;  hx2 = o2*ftanh(cx2);
        cx3 = f3*cx3 + i3*q3;  hx3 = o3*ftanh(cx3);
        float outv = (gate==0)?hx0:(gate==1)?hx1:(gate==2)?hx2:hx3;
        g_hs[((size_t)bat*TT + t)*4 + gate] = outv;
        cur = nxt;
    }
}

// ---------------- logits + log_softmax: one warp per (b,t) -------------------
__global__ void logits_kernel(const float* __restrict__ Wt,
                              const float* __restrict__ bt,
                              float* __restrict__ out)
{
    const int w = (blockIdx.x*blockDim.x + threadIdx.x) >> 5;   // 0..8191
    const int lane = threadIdx.x & 31;
    float4 h = *(const float4*)(g_hs + (size_t)w*4);
    int j0 = lane, j1 = lane + 32;
    float l0 = bt[j0] + h.x*Wt[j0*4+0] + h.y*Wt[j0*4+1] + h.z*Wt[j0*4+2] + h.w*Wt[j0*4+3];
    float l1 = bt[j1] + h.x*Wt[j1*4+0] + h.y*Wt[j1*4+1] + h.z*Wt[j1*4+2] + h.w*Wt[j1*4+3];
    float m = fmaxf(l0, l1);
#pragma unroll
    for (int off=16; off; off>>=1) m = fmaxf(m, __shfl_xor_sync(0xffffffffu, m, off));
    float s = __expf(l0-m) + __expf(l1-m);
#pragma unroll
    for (int off=16; off; off>>=1) s += __shfl_xor_sync(0xffffffffu, s, off);
    float ls = __logf(s) + m;
    out[(size_t)w*64 + j0] = l0 - ls;
    out[(size_t)w*64 + j1] = l1 - ls;
}

// ---------------- launch ------------------------------------------------------
extern "C" void kernel_launch(void* const* d_in, const int* in_sizes, int n_in,
                              void* d_out, int out_size)
{
    (void)in_sizes; (void)n_in; (void)out_size;
    const int*   sentence = (const int*)  d_in[0];
    const float* emb = (const float*)d_in[1];
    const float* Wq  = (const float*)d_in[2];  const float* bq  = (const float*)d_in[3];
    const float* Wk  = (const float*)d_in[4];  const float* bk  = (const float*)d_in[5];
    const float* Wv  = (const float*)d_in[6];  const float* bv  = (const float*)d_in[7];
    const float* Wo  = (const float*)d_in[8];  const float* bo  = (const float*)d_in[9];
    const float* Wf  = (const float*)d_in[10]; const float* bf  = (const float*)d_in[11];
    const float* thf = (const float*)d_in[12];
    const float* Wi  = (const float*)d_in[13]; const float* bi  = (const float*)d_in[14];
    const float* thi = (const float*)d_in[15];
    const float* Wg  = (const float*)d_in[16]; const float* bg  = (const float*)d_in[17];
    const float* thg = (const float*)d_in[18];
    const float* Wo2 = (const float*)d_in[19]; const float* bo2 = (const float*)d_in[20];
    const float* tho = (const float*)d_in[21];
    const float* Wt  = (const float*)d_in[22]; const float* bt  = (const float*)d_in[23];
    float* out = (float*)d_out;

    static bool attr_done = false;
    if (!attr_done){
        cudaFuncSetAttribute(flash_kernel,
                             cudaFuncAttributeMaxDynamicSharedMemorySize, FLASH_SMEM);
        attr_done = true;
    }

    // QKV: grid (M/128=64, N/64=4, 3) on tensor cores
    proj_mma_kernel<<<dim3(64, 4, 3), 256>>>(emb, sentence, Wq, bq, Wk, bk, Wv, bv, 0);
    // fused attention (scores + softmax + PV) on tensor cores
    flash_kernel<<<dim3(4, 64), 256, FLASH_SMEM>>>();
    // O-projection: sel=3, A=g_oc, W=Wo passed in Wq slot
    proj_mma_kernel<<<dim3(64, 4, 1), 256>>>(emb, sentence, Wo, bo, Wk, bk, Wv, bv, 3);
    xproj_kernel<<<1024, 256>>>(Wf,Wi,Wg,Wo2, bf,thf, bi,thi, bg,thg, bo2,tho);
    lstm_kernel<<<2, 32>>>(Wf, Wi, Wg, Wo2);
    logits_kernel<<<1024, 256>>>(Wt, bt, out);
}